// round 4
// baseline (speedup 1.0000x reference)
#include <cuda_runtime.h>
#include <cuda_bf16.h>
#include <math.h>
#include <stdint.h>

#define HID   2048
#define NTOK  8192
#define NH    32
#define HD    64
#define NB    32            /* 8192 / 256 */
#define QKVW  (3*HID)       /* 6144 */

/* ------------------- GEMM tiling (mma.sync bf16 split) --------------------- */
#define BM 128
#define BN 256
#define BK 32
#define ST_A_HI 0
#define ST_A_LO 8192
#define ST_B_HI 16384
#define ST_B_LO 32768
#define STAGE_BYTES 49152           /* 8+8+16+16 KB */
#define NSTAGE 3
#define GEMM_SMEM (NSTAGE*STAGE_BYTES)   /* 144 KB */

/* ------------------------- scratch (device globals) ------------------------ */
__device__ float g_qkv[(size_t)NTOK * QKVW];
__device__ float g_S  [(size_t)NH * NB * HD * HD];
__device__ float g_KV [(size_t)NH * NB * HD * HD];
__device__ float g_hid[(size_t)NTOK * HID];
__device__ float g_rstd[NTOK];
__device__ __nv_bfloat16 g_hs_hi  [(size_t)NTOK * HID];
__device__ __nv_bfloat16 g_hs_lo  [(size_t)NTOK * HID];
__device__ __nv_bfloat16 g_wqkv_hi[(size_t)QKVW * HID];
__device__ __nv_bfloat16 g_wqkv_lo[(size_t)QKVW * HID];
__device__ __nv_bfloat16 g_wg_hi  [(size_t)HID * HID];
__device__ __nv_bfloat16 g_wg_lo  [(size_t)HID * HID];
__device__ __nv_bfloat16 g_wo_hi  [(size_t)HID * HID];
__device__ __nv_bfloat16 g_wo_lo  [(size_t)HID * HID];
__device__ __nv_bfloat16 g_tmp_hi [(size_t)NTOK * HID];
__device__ __nv_bfloat16 g_tmp_lo [(size_t)NTOK * HID];

/* ------------------------------ PTX helpers -------------------------------- */
__device__ __forceinline__ uint32_t smem_u32(const void* p) {
    uint32_t a;
    asm("{ .reg .u64 t; cvta.to.shared.u64 t, %1; cvt.u32.u64 %0, t; }"
        : "=r"(a) : "l"(p));
    return a;
}
__device__ __forceinline__ void cp16(uint32_t dst, const void* src) {
    asm volatile("cp.async.cg.shared.global [%0], [%1], 16;"
                 :: "r"(dst), "l"(src));
}
#define CP_COMMIT()  asm volatile("cp.async.commit_group;" ::: "memory")
#define CP_WAIT(n)   asm volatile("cp.async.wait_group %0;" :: "n"(n) : "memory")

__device__ __forceinline__ void ldsm4(uint32_t* r, uint32_t addr) {
    asm volatile("ldmatrix.sync.aligned.m8n8.x4.shared.b16 {%0,%1,%2,%3}, [%4];"
                 : "=r"(r[0]), "=r"(r[1]), "=r"(r[2]), "=r"(r[3]) : "r"(addr));
}
__device__ __forceinline__ void mma16816(float* d, const uint32_t* a,
                                         const uint32_t* b) {
    asm volatile(
        "mma.sync.aligned.m16n8k16.row.col.f32.bf16.bf16.f32 "
        "{%0,%1,%2,%3}, {%4,%5,%6,%7}, {%8,%9}, {%0,%1,%2,%3};"
        : "+f"(d[0]), "+f"(d[1]), "+f"(d[2]), "+f"(d[3])
        : "r"(a[0]), "r"(a[1]), "r"(a[2]), "r"(a[3]), "r"(b[0]), "r"(b[1]));
}

__device__ __forceinline__ float head_slope(int h) {
    return exp2f(-0.25f * (float)(h + 1)) * 1.00001f;
}

/* tile-contiguous smem layout; A tiles: 16 per kchunk, B tiles: 32 per kchunk */
__device__ __forceinline__ uint32_t sm_off_a(int row, int kch) {
    return ((uint32_t)(kch << 4) + (uint32_t)(row >> 3)) * 128u
         + (uint32_t)(((row & 7) ^ kch) << 4);
}
__device__ __forceinline__ uint32_t sm_off_b(int row, int kch) {
    return ((uint32_t)(kch << 5) + (uint32_t)(row >> 3)) * 128u
         + (uint32_t)(((row & 7) ^ kch) << 4);
}

/* ------------------------ mma.sync split-bf16 GEMM ------------------------- */
/* C[m,n] = epi( sum_k A[m,k]*B[n,k] ), A=[M,K], B=[N,K] bf16 hi/lo pairs.
   EPI 0: C fp32.  EPI 1: silu -> C fp32.
   EPI 2: sigmoid(x)*auxH[m,n]*auxR[m]*auxW[n] -> split into Chi/Clo bf16.   */
template<int EPI>
__global__ void __launch_bounds__(256, 1) mma_gemm_kernel(
    const __nv_bfloat16* __restrict__ Ahi, const __nv_bfloat16* __restrict__ Alo,
    const __nv_bfloat16* __restrict__ Bhi, const __nv_bfloat16* __restrict__ Blo,
    int K, int ldC,
    float* __restrict__ C,
    __nv_bfloat16* __restrict__ Chi, __nv_bfloat16* __restrict__ Clo,
    const float* __restrict__ auxH, const float* __restrict__ auxR,
    const float* __restrict__ auxW)
{
    extern __shared__ char smraw[];
    const uint32_t smu = smem_u32(smraw);
    const int tid  = threadIdx.x;
    const int lane = tid & 31;
    const int wid  = tid >> 5;
    const int m0   = blockIdx.y * BM;
    const int n0   = blockIdx.x * BN;
    const int wm   = (wid >> 2) * 64;      /* 2 warp rows of 64 */
    const int wn   = (wid & 3)  * 64;      /* 4 warp cols of 64 */

    const int r0 = tid >> 2;               /* 0..63 */
    const int kq = tid & 3;                /* 16B chunk within 32-k row */

    float acc[4][8][4];
#pragma unroll
    for (int i = 0; i < 4; i++)
#pragma unroll
        for (int j = 0; j < 8; j++)
#pragma unroll
            for (int v = 0; v < 4; v++) acc[i][j][v] = 0.f;

    const int nch = K / BK;

    /* issue one 32-k chunk into stage s */
    auto issue = [&](int c, int s) {
        const int kc = c * BK;
        const uint32_t sb = smu + (uint32_t)s * STAGE_BYTES;
        /* A: 128 rows */
#pragma unroll
        for (int i = 0; i < 2; i++) {
            const int r = r0 + 64 * i;
            const uint32_t wo = sm_off_a(r, kq);
            const size_t ga = (size_t)(m0 + r) * K + kc + kq * 8;
            cp16(sb + ST_A_HI + wo, Ahi + ga);
            cp16(sb + ST_A_LO + wo, Alo + ga);
        }
        /* B: 256 rows */
#pragma unroll
        for (int i = 0; i < 4; i++) {
            const int r = r0 + 64 * i;
            const uint32_t wo = sm_off_b(r, kq);
            const size_t gb = (size_t)(n0 + r) * K + kc + kq * 8;
            cp16(sb + ST_B_HI + wo, Bhi + gb);
            cp16(sb + ST_B_LO + wo, Blo + gb);
        }
        CP_COMMIT();
    };

    issue(0, 0);
    if (nch > 1) issue(1, 1);
    if (nch > 2) issue(2, 2);

    int buf = 0;
    for (int c = 0; c < nch; c++) {
        if (c < nch - 2)      { CP_WAIT(2); }
        else if (c == nch - 2){ CP_WAIT(1); }
        else                  { CP_WAIT(0); }
        __syncthreads();

        const uint32_t sb = smu + (uint32_t)buf * STAGE_BYTES;
#pragma unroll
        for (int ks = 0; ks < 2; ks++) {
            uint32_t a[4][4], bh[8][2], bl[8][2];
            /* B fragments: 4 halves of 16 cols, hi & lo */
#pragma unroll
            for (int half = 0; half < 4; half++) {
                const int n   = wn + 16*half + ((lane >> 4) << 3) + (lane & 7);
                const int kch = 2*ks + ((lane >> 3) & 1);
                const uint32_t off = sm_off_b(n, kch);
                uint32_t t4[4];
                ldsm4(t4, sb + ST_B_HI + off);
                bh[2*half][0] = t4[0]; bh[2*half][1] = t4[1];
                bh[2*half+1][0] = t4[2]; bh[2*half+1][1] = t4[3];
                ldsm4(t4, sb + ST_B_LO + off);
                bl[2*half][0] = t4[0]; bl[2*half][1] = t4[1];
                bl[2*half+1][0] = t4[2]; bl[2*half+1][1] = t4[3];
            }
            /* A hi fragments */
#pragma unroll
            for (int am = 0; am < 4; am++) {
                const int row = wm + 16*am + (lane & 15);
                const int kch = 2*ks + (lane >> 4);
                ldsm4(a[am], sb + ST_A_HI + sm_off_a(row, kch));
            }
#pragma unroll
            for (int am = 0; am < 4; am++)
#pragma unroll
                for (int bn = 0; bn < 8; bn++) {
                    mma16816(acc[am][bn], a[am], bh[bn]);
                    mma16816(acc[am][bn], a[am], bl[bn]);
                }
            /* A lo fragments (reuse regs) */
#pragma unroll
            for (int am = 0; am < 4; am++) {
                const int row = wm + 16*am + (lane & 15);
                const int kch = 2*ks + (lane >> 4);
                ldsm4(a[am], sb + ST_A_LO + sm_off_a(row, kch));
            }
#pragma unroll
            for (int am = 0; am < 4; am++)
#pragma unroll
                for (int bn = 0; bn < 8; bn++)
                    mma16816(acc[am][bn], a[am], bh[bn]);
        }
        __syncthreads();
        if (c + NSTAGE < nch) issue(c + NSTAGE, buf);
        buf = (buf == NSTAGE - 1) ? 0 : buf + 1;
    }

    /* --------------------------- epilogue ---------------------------------- */
    const int g  = lane >> 2;
    const int t2 = (lane & 3) * 2;
#pragma unroll
    for (int am = 0; am < 4; am++)
#pragma unroll
        for (int bn = 0; bn < 8; bn++) {
            const int n = n0 + wn + 8*bn + t2;
#pragma unroll
            for (int half = 0; half < 2; half++) {
                const int m = m0 + wm + 16*am + g + 8*half;
                const float x0 = acc[am][bn][2*half + 0];
                const float x1 = acc[am][bn][2*half + 1];
                const size_t off = (size_t)m * ldC + n;
                if (EPI == 0) {
                    *(float2*)(C + off) = make_float2(x0, x1);
                } else if (EPI == 1) {
                    *(float2*)(C + off) = make_float2(
                        x0 / (1.f + expf(-x0)), x1 / (1.f + expf(-x1)));
                } else {
                    float2 hv = *(const float2*)(auxH + off);
                    float2 wv = *(const float2*)(auxW + n);
                    float rr = auxR[m];
                    float r0v = hv.x * rr * wv.x / (1.f + expf(-x0));
                    float r1v = hv.y * rr * wv.y / (1.f + expf(-x1));
                    __nv_bfloat16 h0 = __float2bfloat16(r0v);
                    __nv_bfloat16 h1 = __float2bfloat16(r1v);
                    __nv_bfloat162 H, L;
                    H.x = h0; H.y = h1;
                    L.x = __float2bfloat16(r0v - __bfloat162float(h0));
                    L.y = __float2bfloat16(r1v - __bfloat162float(h1));
                    *(__nv_bfloat162*)(Chi + off) = H;
                    *(__nv_bfloat162*)(Clo + off) = L;
                }
            }
        }
}

/* --------------------------- fp32 -> bf16 hi/lo split ----------------------- */
__global__ void __launch_bounds__(256) split_kernel(
    const float4* __restrict__ src, __nv_bfloat162* __restrict__ hi,
    __nv_bfloat162* __restrict__ lo, int n4)
{
    int i = blockIdx.x * blockDim.x + threadIdx.x;
    if (i >= n4) return;
    float4 v = src[i];
    __nv_bfloat16 h0 = __float2bfloat16(v.x), h1 = __float2bfloat16(v.y);
    __nv_bfloat16 h2 = __float2bfloat16(v.z), h3 = __float2bfloat16(v.w);
    __nv_bfloat162 H0, H1, L0, L1;
    H0.x = h0; H0.y = h1; H1.x = h2; H1.y = h3;
    L0.x = __float2bfloat16(v.x - __bfloat162float(h0));
    L0.y = __float2bfloat16(v.y - __bfloat162float(h1));
    L1.x = __float2bfloat16(v.z - __bfloat162float(h2));
    L1.y = __float2bfloat16(v.w - __bfloat162float(h3));
    hi[2*i] = H0; hi[2*i+1] = H1;
    lo[2*i] = L0; lo[2*i+1] = L1;
}

/* ----------------- attention A: per-block KV outer-product sums ------------ */
__global__ void __launch_bounds__(256) attn_kvsum_kernel(
    const float* __restrict__ qkv, float* __restrict__ S)
{
    const int blk = blockIdx.x, h = blockIdx.y;
    __shared__ float Ks[64][65];
    __shared__ float Vs[64][65];
    __shared__ float tab[257];

    const int tid = threadIdx.x;
    const float slope = head_slope(h);
    for (int i = tid; i < 257; i += 256) tab[i] = expf(-slope * (float)i);

    const int tx = tid & 15, ty = tid >> 4;
    float acc[4][4];
#pragma unroll
    for (int i = 0; i < 4; i++)
#pragma unroll
        for (int j = 0; j < 4; j++) acc[i][j] = 0.f;

    for (int nc = 0; nc < 4; nc++) {
        __syncthreads();
        for (int idx = tid; idx < 1024; idx += 256) {
            int n  = idx >> 4;
            int d4 = (idx & 15) << 2;
            int ng = nc*64 + n;
            const float* base = qkv + (size_t)(blk*256 + ng) * QKVW + h*192;
            float4 k4 = *(const float4*)(base + 64 + d4);
            float  kd = tab[255 - ng];
            Ks[n][d4+0] = k4.x*kd; Ks[n][d4+1] = k4.y*kd;
            Ks[n][d4+2] = k4.z*kd; Ks[n][d4+3] = k4.w*kd;
            float4 v4 = *(const float4*)(base + 128 + d4);
            Vs[n][d4+0] = v4.x; Vs[n][d4+1] = v4.y;
            Vs[n][d4+2] = v4.z; Vs[n][d4+3] = v4.w;
        }
        __syncthreads();
#pragma unroll 8
        for (int n = 0; n < 64; n++) {
            float a[4], b[4];
#pragma unroll
            for (int i = 0; i < 4; i++) a[i] = Ks[n][ty*4 + i];
#pragma unroll
            for (int j = 0; j < 4; j++) b[j] = Vs[n][tx*4 + j];
#pragma unroll
            for (int i = 0; i < 4; i++)
#pragma unroll
                for (int j = 0; j < 4; j++) acc[i][j] += a[i]*b[j];
        }
    }
    float* sp = S + ((size_t)h*NB + blk)*4096;
#pragma unroll
    for (int i = 0; i < 4; i++)
        *(float4*)(sp + (ty*4 + i)*64 + tx*4) =
            make_float4(acc[i][0], acc[i][1], acc[i][2], acc[i][3]);
}

/* ---------------- attention B: scan of KV states across blocks ------------- */
__global__ void __launch_bounds__(256) attn_scan_kernel(
    const float* __restrict__ S, const float* __restrict__ kv0,
    float* __restrict__ KV)
{
    const int h = blockIdx.x, tid = threadIdx.x;
    const float bd = expf(-head_slope(h) * 256.f);
    float kv[16];
#pragma unroll
    for (int i = 0; i < 16; i++) kv[i] = kv0[(size_t)h*4096 + tid + i*256];
    for (int j = 0; j < NB; j++) {
        size_t base = ((size_t)h*NB + j)*4096;
#pragma unroll
        for (int i = 0; i < 16; i++) {
            KV[base + tid + i*256] = kv[i];
            kv[i] = bd*kv[i] + S[base + tid + i*256];
        }
    }
}

/* -------- attention C: per (head, block) output tile (inter + intra) ------- */
#define ATTN_SMEM_FLOATS (288 + 2*256*65 + 3*64*65)
#define ATTN_SMEM_BYTES  (ATTN_SMEM_FLOATS * 4)

__global__ void __launch_bounds__(256) attn_out_kernel(
    const float* __restrict__ qkv, const float* __restrict__ KV,
    float* __restrict__ hid)
{
    extern __shared__ float sm[];
    float* tab = sm;
    float* Qs  = sm + 288;
    float* Ps  = Qs + 256*65;
    float* Ks  = Ps + 256*65;
    float* Vs  = Ks + 64*65;
    float* KVs = Vs + 64*65;

    const int blk = blockIdx.x, h = blockIdx.y;
    const int tid = threadIdx.x;
    const float slope = head_slope(h);
    for (int i = tid; i < 257; i += 256) tab[i] = expf(-slope * (float)i);

    for (int idx = tid; idx < 4096; idx += 256) {
        int m = idx >> 4, d4 = (idx & 15) << 2;
        float4 q4 = *(const float4*)(qkv + (size_t)(blk*256 + m)*QKVW + h*192 + d4);
        float* qp = Qs + m*65 + d4;
        qp[0] = q4.x; qp[1] = q4.y; qp[2] = q4.z; qp[3] = q4.w;
    }
    for (int idx = tid; idx < 1024; idx += 256) {
        int d = idx >> 4, e4 = (idx & 15) << 2;
        float4 v4 = *(const float4*)(KV + ((size_t)h*NB + blk)*4096 + d*64 + e4);
        float* kp = KVs + d*65 + e4;
        kp[0] = v4.x; kp[1] = v4.y; kp[2] = v4.z; kp[3] = v4.w;
    }
    __syncthreads();

    const int tx = tid & 7;
    const int ty = tid >> 3;
    const int m0 = ty * 8;

    float acc[8][8];
#pragma unroll
    for (int i = 0; i < 8; i++)
#pragma unroll
        for (int j = 0; j < 8; j++) acc[i][j] = 0.f;

#pragma unroll 4
    for (int d = 0; d < 64; d++) {
        float a[8], b[8];
#pragma unroll
        for (int i = 0; i < 8; i++) a[i] = Qs[(m0 + i)*65 + d];
#pragma unroll
        for (int j = 0; j < 8; j++) b[j] = KVs[d*65 + tx*8 + j];
#pragma unroll
        for (int i = 0; i < 8; i++)
#pragma unroll
            for (int j = 0; j < 8; j++) acc[i][j] += a[i]*b[j];
    }
#pragma unroll
    for (int i = 0; i < 8; i++) {
        float qd = tab[m0 + i + 1];
#pragma unroll
        for (int j = 0; j < 8; j++) acc[i][j] *= qd;
    }

    for (int nc = 0; nc < 4; nc++) {
        __syncthreads();
        for (int idx = tid; idx < 1024; idx += 256) {
            int n = idx >> 4, d4 = (idx & 15) << 2;
            const float* base = qkv + (size_t)(blk*256 + nc*64 + n)*QKVW + h*192;
            float4 k4 = *(const float4*)(base + 64 + d4);
            Ks[(d4+0)*65 + n] = k4.x; Ks[(d4+1)*65 + n] = k4.y;
            Ks[(d4+2)*65 + n] = k4.z; Ks[(d4+3)*65 + n] = k4.w;
            float4 v4 = *(const float4*)(base + 128 + d4);
            float* vp = Vs + n*65 + d4;
            vp[0] = v4.x; vp[1] = v4.y; vp[2] = v4.z; vp[3] = v4.w;
        }
        __syncthreads();

        if (m0 + 7 >= nc*64) {
            float p[8][8];
#pragma unroll
            for (int i = 0; i < 8; i++)
#pragma unroll
                for (int j = 0; j < 8; j++) p[i][j] = 0.f;
#pragma unroll 4
            for (int d = 0; d < 64; d++) {
                float a[8], b[8];
#pragma unroll
                for (int i = 0; i < 8; i++) a[i] = Qs[(m0 + i)*65 + d];
#pragma unroll
                for (int j = 0; j < 8; j++) b[j] = Ks[d*65 + tx*8 + j];
#pragma unroll
                for (int i = 0; i < 8; i++)
#pragma unroll
                    for (int j = 0; j < 8; j++) p[i][j] += a[i]*b[j];
            }
#pragma unroll
            for (int i = 0; i < 8; i++) {
                int mm = m0 + i;
#pragma unroll
                for (int j = 0; j < 8; j++) {
                    int nn = nc*64 + tx*8 + j;
                    int delta = mm - nn;
                    Ps[mm*65 + tx*8 + j] = (delta >= 0) ? p[i][j]*tab[delta] : 0.f;
                }
            }
            __syncwarp();
#pragma unroll 4
            for (int n = 0; n < 64; n++) {
                float a[8], b[8];
#pragma unroll
                for (int i = 0; i < 8; i++) a[i] = Ps[(m0 + i)*65 + n];
#pragma unroll
                for (int j = 0; j < 8; j++) b[j] = Vs[n*65 + tx*8 + j];
#pragma unroll
                for (int i = 0; i < 8; i++)
#pragma unroll
                    for (int j = 0; j < 8; j++) acc[i][j] += a[i]*b[j];
            }
        }
    }

    float* op = hid + (size_t)(blk*256) * HID + h*64;
#pragma unroll
    for (int i = 0; i < 8; i++) {
        float4* dst = (float4*)(op + (size_t)(m0 + i)*HID + tx*8);
        dst[0] = make_float4(acc[i][0], acc[i][1], acc[i][2], acc[i][3]);
        dst[1] = make_float4(acc[i][4], acc[i][5], acc[i][6], acc[i][7]);
    }
}

/* --------------------------- rmsnorm rstd vector --------------------------- */
__global__ void __launch_bounds__(256) rms_kernel(
    const float* __restrict__ hid, float* __restrict__ rstd)
{
    const int row = blockIdx.x, tid = threadIdx.x;
    const float* p = hid + (size_t)row * HID;
    float s = 0.f;
    {
        int i = tid * 8;
        float4 a = *(const float4*)(p + i);
        float4 b = *(const float4*)(p + i + 4);
        s = a.x*a.x + a.y*a.y + a.z*a.z + a.w*a.w
          + b.x*b.x + b.y*b.y + b.z*b.z + b.w*b.w;
    }
#pragma unroll
    for (int off = 16; off; off >>= 1) s += __shfl_xor_sync(~0u, s, off);
    __shared__ float red[8];
    if ((tid & 31) == 0) red[tid >> 5] = s;
    __syncthreads();
    if (tid < 8) {
        float v = red[tid];
#pragma unroll
        for (int off = 4; off; off >>= 1) v += __shfl_xor_sync(0xffu, v, off);
        if (tid == 0) rstd[row] = rsqrtf(v * (1.f / HID) + 1e-5f);
    }
}

/* --------------------------------- launch ---------------------------------- */
extern "C" void kernel_launch(void* const* d_in, const int* in_sizes, int n_in,
                              void* d_out, int out_size)
{
    (void)in_sizes; (void)n_in; (void)out_size;
    const float* hs   = (const float*)d_in[0];
    const float* kv0  = (const float*)d_in[1];
    const float* Wqkv = (const float*)d_in[2];
    const float* Wg   = (const float*)d_in[3];
    const float* Wo   = (const float*)d_in[4];
    const float* nw   = (const float*)d_in[5];
    float* out = (float*)d_out;

    float *qkv, *S, *KV, *hid, *rstd;
    __nv_bfloat16 *hs_hi, *hs_lo, *wq_hi, *wq_lo, *wg_hi, *wg_lo, *wo_hi, *wo_lo;
    __nv_bfloat16 *tmp_hi, *tmp_lo;
    cudaGetSymbolAddress((void**)&qkv,  g_qkv);
    cudaGetSymbolAddress((void**)&S,    g_S);
    cudaGetSymbolAddress((void**)&KV,   g_KV);
    cudaGetSymbolAddress((void**)&hid,  g_hid);
    cudaGetSymbolAddress((void**)&rstd, g_rstd);
    cudaGetSymbolAddress((void**)&hs_hi, g_hs_hi);
    cudaGetSymbolAddress((void**)&hs_lo, g_hs_lo);
    cudaGetSymbolAddress((void**)&wq_hi, g_wqkv_hi);
    cudaGetSymbolAddress((void**)&wq_lo, g_wqkv_lo);
    cudaGetSymbolAddress((void**)&wg_hi, g_wg_hi);
    cudaGetSymbolAddress((void**)&wg_lo, g_wg_lo);
    cudaGetSymbolAddress((void**)&wo_hi, g_wo_hi);
    cudaGetSymbolAddress((void**)&wo_lo, g_wo_lo);
    cudaGetSymbolAddress((void**)&tmp_hi, g_tmp_hi);
    cudaGetSymbolAddress((void**)&tmp_lo, g_tmp_lo);

    cudaFuncSetAttribute(attn_out_kernel,
                         cudaFuncAttributeMaxDynamicSharedMemorySize, ATTN_SMEM_BYTES);
    cudaFuncSetAttribute(mma_gemm_kernel<0>,
                         cudaFuncAttributeMaxDynamicSharedMemorySize, GEMM_SMEM);
    cudaFuncSetAttribute(mma_gemm_kernel<1>,
                         cudaFuncAttributeMaxDynamicSharedMemorySize, GEMM_SMEM);
    cudaFuncSetAttribute(mma_gemm_kernel<2>,
                         cudaFuncAttributeMaxDynamicSharedMemorySize, GEMM_SMEM);

    /* 0. bf16 hi/lo splits */
    split_kernel<<<(NTOK*HID/4 + 255)/256, 256>>>(
        (const float4*)hs, (__nv_bfloat162*)hs_hi, (__nv_bfloat162*)hs_lo, NTOK*HID/4);
    split_kernel<<<(QKVW*HID/4 + 255)/256, 256>>>(
        (const float4*)Wqkv, (__nv_bfloat162*)wq_hi, (__nv_bfloat162*)wq_lo, QKVW*HID/4);
    split_kernel<<<(HID*HID/4 + 255)/256, 256>>>(
        (const float4*)Wg, (__nv_bfloat162*)wg_hi, (__nv_bfloat162*)wg_lo, HID*HID/4);
    split_kernel<<<(HID*HID/4 + 255)/256, 256>>>(
        (const float4*)Wo, (__nv_bfloat162*)wo_hi, (__nv_bfloat162*)wo_lo, HID*HID/4);

    /* 1. qkv = silu(hs @ Wqkv^T) */
    mma_gemm_kernel<1><<<dim3(QKVW/BN, NTOK/BM), 256, GEMM_SMEM>>>(
        hs_hi, hs_lo, wq_hi, wq_lo, HID, QKVW, qkv,
        nullptr, nullptr, nullptr, nullptr, nullptr);

    /* 2-4. lightning attention */
    attn_kvsum_kernel<<<dim3(NB, NH), 256>>>(qkv, S);
    attn_scan_kernel<<<NH, 256>>>(S, kv0, KV);
    attn_out_kernel<<<dim3(NB, NH), 256, ATTN_SMEM_BYTES>>>(qkv, KV, hid);

    /* 5. rmsnorm scale vector */
    rms_kernel<<<NTOK, 256>>>(hid, rstd);

    /* 6. tmp = sigmoid(hs @ Wg^T) * hid * rstd * nw -> bf16 hi/lo */
    mma_gemm_kernel<2><<<dim3(HID/BN, NTOK/BM), 256, GEMM_SMEM>>>(
        hs_hi, hs_lo, wg_hi, wg_lo, HID, HID, nullptr,
        tmp_hi, tmp_lo, hid, rstd, nw);

    /* 7. out = tmp @ Wo^T */
    mma_gemm_kernel<0><<<dim3(HID/BN, NTOK/BM), 256, GEMM_SMEM>>>(
        tmp_hi, tmp_lo, wo_hi, wo_lo, HID, HID, out,
        nullptr, nullptr, nullptr, nullptr, nullptr);
}

// round 5
// speedup vs baseline: 1.0161x; 1.0161x over previous
#include <cuda_runtime.h>
#include <cuda_bf16.h>
#include <math.h>
#include <stdint.h>

#define HID   2048
#define NTOK  8192
#define NH    32
#define HD    64
#define NB    32            /* 8192 / 256 */
#define QKVW  (3*HID)       /* 6144 */

/* ------------------- GEMM tiling (mma.sync bf16 split) --------------------- */
#define GTHREADS 512
#define BM 128
#define BN 256
#define BK 32
#define ST_A_HI 0
#define ST_A_LO 8192
#define ST_B_HI 16384
#define ST_B_LO 32768
#define STAGE_BYTES 49152           /* 8+8+16+16 KB */
#define NSTAGE 4
#define GEMM_SMEM (NSTAGE*STAGE_BYTES)   /* 192 KB */

/* ------------------------- scratch (device globals) ------------------------ */
__device__ float g_qkv[(size_t)NTOK * QKVW];
__device__ float g_S  [(size_t)NH * NB * HD * HD];
__device__ float g_KV [(size_t)NH * NB * HD * HD];
__device__ float g_hid[(size_t)NTOK * HID];
__device__ float g_rstd[NTOK];
__device__ __nv_bfloat16 g_hs_hi  [(size_t)NTOK * HID];
__device__ __nv_bfloat16 g_hs_lo  [(size_t)NTOK * HID];
__device__ __nv_bfloat16 g_wqkv_hi[(size_t)QKVW * HID];
__device__ __nv_bfloat16 g_wqkv_lo[(size_t)QKVW * HID];
__device__ __nv_bfloat16 g_wg_hi  [(size_t)HID * HID];
__device__ __nv_bfloat16 g_wg_lo  [(size_t)HID * HID];
__device__ __nv_bfloat16 g_wo_hi  [(size_t)HID * HID];
__device__ __nv_bfloat16 g_wo_lo  [(size_t)HID * HID];
__device__ __nv_bfloat16 g_tmp_hi [(size_t)NTOK * HID];
__device__ __nv_bfloat16 g_tmp_lo [(size_t)NTOK * HID];

/* ------------------------------ PTX helpers -------------------------------- */
__device__ __forceinline__ uint32_t smem_u32(const void* p) {
    uint32_t a;
    asm("{ .reg .u64 t; cvta.to.shared.u64 t, %1; cvt.u32.u64 %0, t; }"
        : "=r"(a) : "l"(p));
    return a;
}
__device__ __forceinline__ void cp16(uint32_t dst, const void* src) {
    asm volatile("cp.async.cg.shared.global [%0], [%1], 16;"
                 :: "r"(dst), "l"(src));
}
#define CP_COMMIT()  asm volatile("cp.async.commit_group;" ::: "memory")
#define CP_WAIT(n)   asm volatile("cp.async.wait_group %0;" :: "n"(n) : "memory")

__device__ __forceinline__ void ldsm4(uint32_t* r, uint32_t addr) {
    asm volatile("ldmatrix.sync.aligned.m8n8.x4.shared.b16 {%0,%1,%2,%3}, [%4];"
                 : "=r"(r[0]), "=r"(r[1]), "=r"(r[2]), "=r"(r[3]) : "r"(addr));
}
__device__ __forceinline__ void mma16816(float* d, const uint32_t* a,
                                         const uint32_t* b) {
    asm volatile(
        "mma.sync.aligned.m16n8k16.row.col.f32.bf16.bf16.f32 "
        "{%0,%1,%2,%3}, {%4,%5,%6,%7}, {%8,%9}, {%0,%1,%2,%3};"
        : "+f"(d[0]), "+f"(d[1]), "+f"(d[2]), "+f"(d[3])
        : "r"(a[0]), "r"(a[1]), "r"(a[2]), "r"(a[3]), "r"(b[0]), "r"(b[1]));
}

__device__ __forceinline__ float head_slope(int h) {
    return exp2f(-0.25f * (float)(h + 1)) * 1.00001f;
}

/* tile-contiguous smem layout; A: 16 tiles per kchunk, B: 32 tiles per kchunk */
__device__ __forceinline__ uint32_t sm_off_a(int row, int kch) {
    return ((uint32_t)(kch << 4) + (uint32_t)(row >> 3)) * 128u
         + (uint32_t)(((row & 7) ^ kch) << 4);
}
__device__ __forceinline__ uint32_t sm_off_b(int row, int kch) {
    return ((uint32_t)(kch << 5) + (uint32_t)(row >> 3)) * 128u
         + (uint32_t)(((row & 7) ^ kch) << 4);
}

/* ------------------------ mma.sync split-bf16 GEMM ------------------------- */
/* C[m,n] = epi( sum_k A[m,k]*B[n,k] ), A=[M,K], B=[N,K] bf16 hi/lo pairs.
   EPI 0: C fp32.  EPI 1: silu -> C fp32.
   EPI 2: sigmoid(x)*auxH[m,n]*auxR[m]*auxW[n] -> split into Chi/Clo bf16.   */
template<int EPI>
__global__ void __launch_bounds__(GTHREADS, 1) mma_gemm_kernel(
    const __nv_bfloat16* __restrict__ Ahi, const __nv_bfloat16* __restrict__ Alo,
    const __nv_bfloat16* __restrict__ Bhi, const __nv_bfloat16* __restrict__ Blo,
    int K, int ldC,
    float* __restrict__ C,
    __nv_bfloat16* __restrict__ Chi, __nv_bfloat16* __restrict__ Clo,
    const float* __restrict__ auxH, const float* __restrict__ auxR,
    const float* __restrict__ auxW)
{
    extern __shared__ char smraw[];
    const uint32_t smu = smem_u32(smraw);
    const int tid  = threadIdx.x;
    const int lane = tid & 31;
    const int wid  = tid >> 5;              /* 0..15 */
    const int m0   = blockIdx.y * BM;
    const int n0   = blockIdx.x * BN;
    const int wm   = (wid >> 3) * 64;       /* 2 warp rows of 64 */
    const int wn   = (wid & 7)  * 32;       /* 8 warp cols of 32 */

    const int r0 = tid >> 2;                /* 0..127 */
    const int kq = tid & 3;                 /* 16B chunk within 32-k row */

    float acc[4][4][4];
#pragma unroll
    for (int i = 0; i < 4; i++)
#pragma unroll
        for (int j = 0; j < 4; j++)
#pragma unroll
            for (int v = 0; v < 4; v++) acc[i][j][v] = 0.f;

    const int nch = K / BK;

    /* issue one 32-k chunk into stage s (each thread: 2 A + 4 B cp16) */
    auto issue = [&](int c, int s) {
        const int kc = c * BK;
        const uint32_t sb = smu + (uint32_t)s * STAGE_BYTES;
        {   /* A: 128 rows */
            const uint32_t wo = sm_off_a(r0, kq);
            const size_t ga = (size_t)(m0 + r0) * K + kc + kq * 8;
            cp16(sb + ST_A_HI + wo, Ahi + ga);
            cp16(sb + ST_A_LO + wo, Alo + ga);
        }
#pragma unroll
        for (int i = 0; i < 2; i++) {        /* B: 256 rows */
            const int r = r0 + 128 * i;
            const uint32_t wo = sm_off_b(r, kq);
            const size_t gb = (size_t)(n0 + r) * K + kc + kq * 8;
            cp16(sb + ST_B_HI + wo, Bhi + gb);
            cp16(sb + ST_B_LO + wo, Blo + gb);
        }
        CP_COMMIT();
    };

    issue(0, 0);
    if (nch > 1) issue(1, 1);
    if (nch > 2) issue(2, 2);

    for (int c = 0; c < nch; c++) {
        if (c + 2 < nch)      { CP_WAIT(2); }
        else if (c + 1 < nch) { CP_WAIT(1); }
        else                  { CP_WAIT(0); }
        __syncthreads();
        /* refill the slot consumed at iteration c-1 */
        if (c + 3 < nch) issue(c + 3, (c + 3) & 3);

        const uint32_t sb = smu + (uint32_t)(c & 3) * STAGE_BYTES;
#pragma unroll
        for (int ks = 0; ks < 2; ks++) {
            uint32_t a[4][4], bh[4][2], bl[4][2];
            /* B fragments: 2 halves of 16 cols, hi & lo */
#pragma unroll
            for (int half = 0; half < 2; half++) {
                const int n   = wn + 16*half + ((lane >> 4) << 3) + (lane & 7);
                const int kch = 2*ks + ((lane >> 3) & 1);
                const uint32_t off = sm_off_b(n, kch);
                uint32_t t4[4];
                ldsm4(t4, sb + ST_B_HI + off);
                bh[2*half][0] = t4[0]; bh[2*half][1] = t4[1];
                bh[2*half+1][0] = t4[2]; bh[2*half+1][1] = t4[3];
                ldsm4(t4, sb + ST_B_LO + off);
                bl[2*half][0] = t4[0]; bl[2*half][1] = t4[1];
                bl[2*half+1][0] = t4[2]; bl[2*half+1][1] = t4[3];
            }
            /* A hi fragments */
#pragma unroll
            for (int am = 0; am < 4; am++) {
                const int row = wm + 16*am + (lane & 15);
                const int kch = 2*ks + (lane >> 4);
                ldsm4(a[am], sb + ST_A_HI + sm_off_a(row, kch));
            }
#pragma unroll
            for (int am = 0; am < 4; am++)
#pragma unroll
                for (int bn = 0; bn < 4; bn++) {
                    mma16816(acc[am][bn], a[am], bh[bn]);
                    mma16816(acc[am][bn], a[am], bl[bn]);
                }
            /* A lo fragments (reuse regs) */
#pragma unroll
            for (int am = 0; am < 4; am++) {
                const int row = wm + 16*am + (lane & 15);
                const int kch = 2*ks + (lane >> 4);
                ldsm4(a[am], sb + ST_A_LO + sm_off_a(row, kch));
            }
#pragma unroll
            for (int am = 0; am < 4; am++)
#pragma unroll
                for (int bn = 0; bn < 4; bn++)
                    mma16816(acc[am][bn], a[am], bh[bn]);
        }
    }

    /* --------------------------- epilogue ---------------------------------- */
    const int g  = lane >> 2;
    const int t2 = (lane & 3) * 2;
#pragma unroll
    for (int am = 0; am < 4; am++)
#pragma unroll
        for (int bn = 0; bn < 4; bn++) {
            const int n = n0 + wn + 8*bn + t2;
#pragma unroll
            for (int half = 0; half < 2; half++) {
                const int m = m0 + wm + 16*am + g + 8*half;
                const float x0 = acc[am][bn][2*half + 0];
                const float x1 = acc[am][bn][2*half + 1];
                const size_t off = (size_t)m * ldC + n;
                if (EPI == 0) {
                    *(float2*)(C + off) = make_float2(x0, x1);
                } else if (EPI == 1) {
                    *(float2*)(C + off) = make_float2(
                        x0 / (1.f + expf(-x0)), x1 / (1.f + expf(-x1)));
                } else {
                    float2 hv = *(const float2*)(auxH + off);
                    float2 wv = *(const float2*)(auxW + n);
                    float rr = auxR[m];
                    float r0v = hv.x * rr * wv.x / (1.f + expf(-x0));
                    float r1v = hv.y * rr * wv.y / (1.f + expf(-x1));
                    __nv_bfloat16 h0 = __float2bfloat16(r0v);
                    __nv_bfloat16 h1 = __float2bfloat16(r1v);
                    __nv_bfloat162 H, L;
                    H.x = h0; H.y = h1;
                    L.x = __float2bfloat16(r0v - __bfloat162float(h0));
                    L.y = __float2bfloat16(r1v - __bfloat162float(h1));
                    *(__nv_bfloat162*)(Chi + off) = H;
                    *(__nv_bfloat162*)(Clo + off) = L;
                }
            }
        }
}

/* --------------------------- fp32 -> bf16 hi/lo split ----------------------- */
__global__ void __launch_bounds__(256) split_kernel(
    const float4* __restrict__ src, __nv_bfloat162* __restrict__ hi,
    __nv_bfloat162* __restrict__ lo, int n4)
{
    int i = blockIdx.x * blockDim.x + threadIdx.x;
    if (i >= n4) return;
    float4 v = src[i];
    __nv_bfloat16 h0 = __float2bfloat16(v.x), h1 = __float2bfloat16(v.y);
    __nv_bfloat16 h2 = __float2bfloat16(v.z), h3 = __float2bfloat16(v.w);
    __nv_bfloat162 H0, H1, L0, L1;
    H0.x = h0; H0.y = h1; H1.x = h2; H1.y = h3;
    L0.x = __float2bfloat16(v.x - __bfloat162float(h0));
    L0.y = __float2bfloat16(v.y - __bfloat162float(h1));
    L1.x = __float2bfloat16(v.z - __bfloat162float(h2));
    L1.y = __float2bfloat16(v.w - __bfloat162float(h3));
    hi[2*i] = H0; hi[2*i+1] = H1;
    lo[2*i] = L0; lo[2*i+1] = L1;
}

/* ----------------- attention A: per-block KV outer-product sums ------------ */
__global__ void __launch_bounds__(256) attn_kvsum_kernel(
    const float* __restrict__ qkv, float* __restrict__ S)
{
    const int blk = blockIdx.x, h = blockIdx.y;
    __shared__ float Ks[64][65];
    __shared__ float Vs[64][65];
    __shared__ float tab[257];

    const int tid = threadIdx.x;
    const float slope = head_slope(h);
    for (int i = tid; i < 257; i += 256) tab[i] = expf(-slope * (float)i);

    const int tx = tid & 15, ty = tid >> 4;
    float acc[4][4];
#pragma unroll
    for (int i = 0; i < 4; i++)
#pragma unroll
        for (int j = 0; j < 4; j++) acc[i][j] = 0.f;

    for (int nc = 0; nc < 4; nc++) {
        __syncthreads();
        for (int idx = tid; idx < 1024; idx += 256) {
            int n  = idx >> 4;
            int d4 = (idx & 15) << 2;
            int ng = nc*64 + n;
            const float* base = qkv + (size_t)(blk*256 + ng) * QKVW + h*192;
            float4 k4 = *(const float4*)(base + 64 + d4);
            float  kd = tab[255 - ng];
            Ks[n][d4+0] = k4.x*kd; Ks[n][d4+1] = k4.y*kd;
            Ks[n][d4+2] = k4.z*kd; Ks[n][d4+3] = k4.w*kd;
            float4 v4 = *(const float4*)(base + 128 + d4);
            Vs[n][d4+0] = v4.x; Vs[n][d4+1] = v4.y;
            Vs[n][d4+2] = v4.z; Vs[n][d4+3] = v4.w;
        }
        __syncthreads();
#pragma unroll 8
        for (int n = 0; n < 64; n++) {
            float a[4], b[4];
#pragma unroll
            for (int i = 0; i < 4; i++) a[i] = Ks[n][ty*4 + i];
#pragma unroll
            for (int j = 0; j < 4; j++) b[j] = Vs[n][tx*4 + j];
#pragma unroll
            for (int i = 0; i < 4; i++)
#pragma unroll
                for (int j = 0; j < 4; j++) acc[i][j] += a[i]*b[j];
        }
    }
    float* sp = S + ((size_t)h*NB + blk)*4096;
#pragma unroll
    for (int i = 0; i < 4; i++)
        *(float4*)(sp + (ty*4 + i)*64 + tx*4) =
            make_float4(acc[i][0], acc[i][1], acc[i][2], acc[i][3]);
}

/* ---------------- attention B: scan of KV states across blocks ------------- */
__global__ void __launch_bounds__(256) attn_scan_kernel(
    const float* __restrict__ S, const float* __restrict__ kv0,
    float* __restrict__ KV)
{
    const int h = blockIdx.x, tid = threadIdx.x;
    const float bd = expf(-head_slope(h) * 256.f);
    float kv[16];
#pragma unroll
    for (int i = 0; i < 16; i++) kv[i] = kv0[(size_t)h*4096 + tid + i*256];
    for (int j = 0; j < NB; j++) {
        size_t base = ((size_t)h*NB + j)*4096;
#pragma unroll
        for (int i = 0; i < 16; i++) {
            KV[base + tid + i*256] = kv[i];
            kv[i] = bd*kv[i] + S[base + tid + i*256];
        }
    }
}

/* -------- attention C: per (head, block) output tile (inter + intra) ------- */
#define ATTN_SMEM_FLOATS (288 + 2*256*65 + 3*64*65)
#define ATTN_SMEM_BYTES  (ATTN_SMEM_FLOATS * 4)

__global__ void __launch_bounds__(256) attn_out_kernel(
    const float* __restrict__ qkv, const float* __restrict__ KV,
    float* __restrict__ hid)
{
    extern __shared__ float sm[];
    float* tab = sm;
    float* Qs  = sm + 288;
    float* Ps  = Qs + 256*65;
    float* Ks  = Ps + 256*65;
    float* Vs  = Ks + 64*65;
    float* KVs = Vs + 64*65;

    const int blk = blockIdx.x, h = blockIdx.y;
    const int tid = threadIdx.x;
    const float slope = head_slope(h);
    for (int i = tid; i < 257; i += 256) tab[i] = expf(-slope * (float)i);

    for (int idx = tid; idx < 4096; idx += 256) {
        int m = idx >> 4, d4 = (idx & 15) << 2;
        float4 q4 = *(const float4*)(qkv + (size_t)(blk*256 + m)*QKVW + h*192 + d4);
        float* qp = Qs + m*65 + d4;
        qp[0] = q4.x; qp[1] = q4.y; qp[2] = q4.z; qp[3] = q4.w;
    }
    for (int idx = tid; idx < 1024; idx += 256) {
        int d = idx >> 4, e4 = (idx & 15) << 2;
        float4 v4 = *(const float4*)(KV + ((size_t)h*NB + blk)*4096 + d*64 + e4);
        float* kp = KVs + d*65 + e4;
        kp[0] = v4.x; kp[1] = v4.y; kp[2] = v4.z; kp[3] = v4.w;
    }
    __syncthreads();

    const int tx = tid & 7;
    const int ty = tid >> 3;
    const int m0 = ty * 8;

    float acc[8][8];
#pragma unroll
    for (int i = 0; i < 8; i++)
#pragma unroll
        for (int j = 0; j < 8; j++) acc[i][j] = 0.f;

#pragma unroll 4
    for (int d = 0; d < 64; d++) {
        float a[8], b[8];
#pragma unroll
        for (int i = 0; i < 8; i++) a[i] = Qs[(m0 + i)*65 + d];
#pragma unroll
        for (int j = 0; j < 8; j++) b[j] = KVs[d*65 + tx*8 + j];
#pragma unroll
        for (int i = 0; i < 8; i++)
#pragma unroll
            for (int j = 0; j < 8; j++) acc[i][j] += a[i]*b[j];
    }
#pragma unroll
    for (int i = 0; i < 8; i++) {
        float qd = tab[m0 + i + 1];
#pragma unroll
        for (int j = 0; j < 8; j++) acc[i][j] *= qd;
    }

    for (int nc = 0; nc < 4; nc++) {
        __syncthreads();
        for (int idx = tid; idx < 1024; idx += 256) {
            int n = idx >> 4, d4 = (idx & 15) << 2;
            const float* base = qkv + (size_t)(blk*256 + nc*64 + n)*QKVW + h*192;
            float4 k4 = *(const float4*)(base + 64 + d4);
            Ks[(d4+0)*65 + n] = k4.x; Ks[(d4+1)*65 + n] = k4.y;
            Ks[(d4+2)*65 + n] = k4.z; Ks[(d4+3)*65 + n] = k4.w;
            float4 v4 = *(const float4*)(base + 128 + d4);
            float* vp = Vs + n*65 + d4;
            vp[0] = v4.x; vp[1] = v4.y; vp[2] = v4.z; vp[3] = v4.w;
        }
        __syncthreads();

        if (m0 + 7 >= nc*64) {
            float p[8][8];
#pragma unroll
            for (int i = 0; i < 8; i++)
#pragma unroll
                for (int j = 0; j < 8; j++) p[i][j] = 0.f;
#pragma unroll 4
            for (int d = 0; d < 64; d++) {
                float a[8], b[8];
#pragma unroll
                for (int i = 0; i < 8; i++) a[i] = Qs[(m0 + i)*65 + d];
#pragma unroll
                for (int j = 0; j < 8; j++) b[j] = Ks[d*65 + tx*8 + j];
#pragma unroll
                for (int i = 0; i < 8; i++)
#pragma unroll
                    for (int j = 0; j < 8; j++) p[i][j] += a[i]*b[j];
            }
#pragma unroll
            for (int i = 0; i < 8; i++) {
                int mm = m0 + i;
#pragma unroll
                for (int j = 0; j < 8; j++) {
                    int nn = nc*64 + tx*8 + j;
                    int delta = mm - nn;
                    Ps[mm*65 + tx*8 + j] = (delta >= 0) ? p[i][j]*tab[delta] : 0.f;
                }
            }
            __syncwarp();
#pragma unroll 4
            for (int n = 0; n < 64; n++) {
                float a[8], b[8];
#pragma unroll
                for (int i = 0; i < 8; i++) a[i] = Ps[(m0 + i)*65 + n];
#pragma unroll
                for (int j = 0; j < 8; j++) b[j] = Vs[n*65 + tx*8 + j];
#pragma unroll
                for (int i = 0; i < 8; i++)
#pragma unroll
                    for (int j = 0; j < 8; j++) acc[i][j] += a[i]*b[j];
            }
        }
    }

    float* op = hid + (size_t)(blk*256) * HID + h*64;
#pragma unroll
    for (int i = 0; i < 8; i++) {
        float4* dst = (float4*)(op + (size_t)(m0 + i)*HID + tx*8);
        dst[0] = make_float4(acc[i][0], acc[i][1], acc[i][2], acc[i][3]);
        dst[1] = make_float4(acc[i][4], acc[i][5], acc[i][6], acc[i][7]);
    }
}

/* --------------------------- rmsnorm rstd vector --------------------------- */
__global__ void __launch_bounds__(256) rms_kernel(
    const float* __restrict__ hid, float* __restrict__ rstd)
{
    const int row = blockIdx.x, tid = threadIdx.x;
    const float* p = hid + (size_t)row * HID;
    float s = 0.f;
    {
        int i = tid * 8;
        float4 a = *(const float4*)(p + i);
        float4 b = *(const float4*)(p + i + 4);
        s = a.x*a.x + a.y*a.y + a.z*a.z + a.w*a.w
          + b.x*b.x + b.y*b.y + b.z*b.z + b.w*b.w;
    }
#pragma unroll
    for (int off = 16; off; off >>= 1) s += __shfl_xor_sync(~0u, s, off);
    __shared__ float red[8];
    if ((tid & 31) == 0) red[tid >> 5] = s;
    __syncthreads();
    if (tid < 8) {
        float v = red[tid];
#pragma unroll
        for (int off = 4; off; off >>= 1) v += __shfl_xor_sync(0xffu, v, off);
        if (tid == 0) rstd[row] = rsqrtf(v * (1.f / HID) + 1e-5f);
    }
}

/* --------------------------------- launch ---------------------------------- */
extern "C" void kernel_launch(void* const* d_in, const int* in_sizes, int n_in,
                              void* d_out, int out_size)
{
    (void)in_sizes; (void)n_in; (void)out_size;
    const float* hs   = (const float*)d_in[0];
    const float* kv0  = (const float*)d_in[1];
    const float* Wqkv = (const float*)d_in[2];
    const float* Wg   = (const float*)d_in[3];
    const float* Wo   = (const float*)d_in[4];
    const float* nw   = (const float*)d_in[5];
    float* out = (float*)d_out;

    float *qkv, *S, *KV, *hid, *rstd;
    __nv_bfloat16 *hs_hi, *hs_lo, *wq_hi, *wq_lo, *wg_hi, *wg_lo, *wo_hi, *wo_lo;
    __nv_bfloat16 *tmp_hi, *tmp_lo;
    cudaGetSymbolAddress((void**)&qkv,  g_qkv);
    cudaGetSymbolAddress((void**)&S,    g_S);
    cudaGetSymbolAddress((void**)&KV,   g_KV);
    cudaGetSymbolAddress((void**)&hid,  g_hid);
    cudaGetSymbolAddress((void**)&rstd, g_rstd);
    cudaGetSymbolAddress((void**)&hs_hi, g_hs_hi);
    cudaGetSymbolAddress((void**)&hs_lo, g_hs_lo);
    cudaGetSymbolAddress((void**)&wq_hi, g_wqkv_hi);
    cudaGetSymbolAddress((void**)&wq_lo, g_wqkv_lo);
    cudaGetSymbolAddress((void**)&wg_hi, g_wg_hi);
    cudaGetSymbolAddress((void**)&wg_lo, g_wg_lo);
    cudaGetSymbolAddress((void**)&wo_hi, g_wo_hi);
    cudaGetSymbolAddress((void**)&wo_lo, g_wo_lo);
    cudaGetSymbolAddress((void**)&tmp_hi, g_tmp_hi);
    cudaGetSymbolAddress((void**)&tmp_lo, g_tmp_lo);

    cudaFuncSetAttribute(attn_out_kernel,
                         cudaFuncAttributeMaxDynamicSharedMemorySize, ATTN_SMEM_BYTES);
    cudaFuncSetAttribute(mma_gemm_kernel<0>,
                         cudaFuncAttributeMaxDynamicSharedMemorySize, GEMM_SMEM);
    cudaFuncSetAttribute(mma_gemm_kernel<1>,
                         cudaFuncAttributeMaxDynamicSharedMemorySize, GEMM_SMEM);
    cudaFuncSetAttribute(mma_gemm_kernel<2>,
                         cudaFuncAttributeMaxDynamicSharedMemorySize, GEMM_SMEM);

    /* 0. bf16 hi/lo splits */
    split_kernel<<<(NTOK*HID/4 + 255)/256, 256>>>(
        (const float4*)hs, (__nv_bfloat162*)hs_hi, (__nv_bfloat162*)hs_lo, NTOK*HID/4);
    split_kernel<<<(QKVW*HID/4 + 255)/256, 256>>>(
        (const float4*)Wqkv, (__nv_bfloat162*)wq_hi, (__nv_bfloat162*)wq_lo, QKVW*HID/4);
    split_kernel<<<(HID*HID/4 + 255)/256, 256>>>(
        (const float4*)Wg, (__nv_bfloat162*)wg_hi, (__nv_bfloat162*)wg_lo, HID*HID/4);
    split_kernel<<<(HID*HID/4 + 255)/256, 256>>>(
        (const float4*)Wo, (__nv_bfloat162*)wo_hi, (__nv_bfloat162*)wo_lo, HID*HID/4);

    /* 1. qkv = silu(hs @ Wqkv^T) */
    mma_gemm_kernel<1><<<dim3(QKVW/BN, NTOK/BM), GTHREADS, GEMM_SMEM>>>(
        hs_hi, hs_lo, wq_hi, wq_lo, HID, QKVW, qkv,
        nullptr, nullptr, nullptr, nullptr, nullptr);

    /* 2-4. lightning attention */
    attn_kvsum_kernel<<<dim3(NB, NH), 256>>>(qkv, S);
    attn_scan_kernel<<<NH, 256>>>(S, kv0, KV);
    attn_out_kernel<<<dim3(NB, NH), 256, ATTN_SMEM_BYTES>>>(qkv, KV, hid);

    /* 5. rmsnorm scale vector */
    rms_kernel<<<NTOK, 256>>>(hid, rstd);

    /* 6. tmp = sigmoid(hs @ Wg^T) * hid * rstd * nw -> bf16 hi/lo */
    mma_gemm_kernel<2><<<dim3(HID/BN, NTOK/BM), GTHREADS, GEMM_SMEM>>>(
        hs_hi, hs_lo, wg_hi, wg_lo, HID, HID, nullptr,
        tmp_hi, tmp_lo, hid, rstd, nw);

    /* 7. out = tmp @ Wo^T */
    mma_gemm_kernel<0><<<dim3(HID/BN, NTOK/BM), GTHREADS, GEMM_SMEM>>>(
        tmp_hi, tmp_lo, wo_hi, wo_lo, HID, HID, out,
        nullptr, nullptr, nullptr, nullptr, nullptr);
}

// round 6
// speedup vs baseline: 1.0566x; 1.0399x over previous
#include <cuda_runtime.h>
#include <cuda_bf16.h>
#include <math.h>
#include <stdint.h>

#define HID   2048
#define NTOK  8192
#define NH    32
#define HD    64
#define NB    32            /* 8192 / 256 */
#define QKVW  (3*HID)       /* 6144 */

/* ------------------- GEMM tiling (mma.sync bf16 split) --------------------- */
#define BM 128
#define BN 128
#define BK 32
#define ST_A_HI 0
#define ST_A_LO 8192
#define ST_B_HI 16384
#define ST_B_LO 24576
#define STAGE_BYTES 32768
#define GEMM_SMEM (2*STAGE_BYTES)     /* 64 KB */

/* ------------------------- scratch (device globals) ------------------------ */
__device__ float g_qkv[(size_t)NTOK * QKVW];
__device__ float g_S  [(size_t)NH * NB * HD * HD];
__device__ float g_KV [(size_t)NH * NB * HD * HD];
__device__ float g_hid[(size_t)NTOK * HID];
__device__ float g_rstd[NTOK];
__device__ __nv_bfloat16 g_hs_hi  [(size_t)NTOK * HID];
__device__ __nv_bfloat16 g_hs_lo  [(size_t)NTOK * HID];
__device__ __nv_bfloat16 g_wqkv_hi[(size_t)QKVW * HID];
__device__ __nv_bfloat16 g_wqkv_lo[(size_t)QKVW * HID];
__device__ __nv_bfloat16 g_wg_hi  [(size_t)HID * HID];
__device__ __nv_bfloat16 g_wg_lo  [(size_t)HID * HID];
__device__ __nv_bfloat16 g_wo_hi  [(size_t)HID * HID];
__device__ __nv_bfloat16 g_wo_lo  [(size_t)HID * HID];
__device__ __nv_bfloat16 g_tmp_hi [(size_t)NTOK * HID];
__device__ __nv_bfloat16 g_tmp_lo [(size_t)NTOK * HID];

/* ------------------------------ PTX helpers -------------------------------- */
__device__ __forceinline__ uint32_t smem_u32(const void* p) {
    uint32_t a;
    asm("{ .reg .u64 t; cvta.to.shared.u64 t, %1; cvt.u32.u64 %0, t; }"
        : "=r"(a) : "l"(p));
    return a;
}
__device__ __forceinline__ void cp16(uint32_t dst, const void* src) {
    asm volatile("cp.async.cg.shared.global [%0], [%1], 16;"
                 :: "r"(dst), "l"(src));
}
#define CP_COMMIT()  asm volatile("cp.async.commit_group;" ::: "memory")
#define CP_WAIT(n)   asm volatile("cp.async.wait_group %0;" :: "n"(n) : "memory")

__device__ __forceinline__ void ldsm4(uint32_t* r, uint32_t addr) {
    asm volatile("ldmatrix.sync.aligned.m8n8.x4.shared.b16 {%0,%1,%2,%3}, [%4];"
                 : "=r"(r[0]), "=r"(r[1]), "=r"(r[2]), "=r"(r[3]) : "r"(addr));
}
__device__ __forceinline__ void mma16816(float* d, const uint32_t* a,
                                         const uint32_t* b) {
    asm volatile(
        "mma.sync.aligned.m16n8k16.row.col.f32.bf16.bf16.f32 "
        "{%0,%1,%2,%3}, {%4,%5,%6,%7}, {%8,%9}, {%0,%1,%2,%3};"
        : "+f"(d[0]), "+f"(d[1]), "+f"(d[2]), "+f"(d[3])
        : "r"(a[0]), "r"(a[1]), "r"(a[2]), "r"(a[3]), "r"(b[0]), "r"(b[1]));
}

__device__ __forceinline__ float head_slope(int h) {
    return exp2f(-0.25f * (float)(h + 1)) * 1.00001f;
}

/* tile-contiguous smem layout: tile(kch, tr) at (kch*16 + tr)*128 bytes,
   within-tile row slot = (row&7) ^ kch (both loads & stores use it).       */
__device__ __forceinline__ uint32_t sm_off(int row, int kch) {
    return ((uint32_t)(kch << 4) + (uint32_t)(row >> 3)) * 128u
         + (uint32_t)(((row & 7) ^ kch) << 4);
}

/* ------------------------ mma.sync split-bf16 GEMM ------------------------- */
/* C[m,n] = epi( sum_k A[m,k]*B[n,k] ), A=[M,K], B=[N,K] bf16 hi/lo pairs.
   EPI 0: C fp32.  EPI 1: silu -> C fp32.
   EPI 2: sigmoid(x)*auxH[m,n]*auxR[m]*auxW[n] -> split into Chi/Clo bf16.   */
template<int EPI>
__global__ void __launch_bounds__(256, 2) mma_gemm_kernel(
    const __nv_bfloat16* __restrict__ Ahi, const __nv_bfloat16* __restrict__ Alo,
    const __nv_bfloat16* __restrict__ Bhi, const __nv_bfloat16* __restrict__ Blo,
    int K, int ldC,
    float* __restrict__ C,
    __nv_bfloat16* __restrict__ Chi, __nv_bfloat16* __restrict__ Clo,
    const float* __restrict__ auxH, const float* __restrict__ auxR,
    const float* __restrict__ auxW)
{
    extern __shared__ char smraw[];
    const uint32_t smu = smem_u32(smraw);
    const int tid  = threadIdx.x;
    const int lane = tid & 31;
    const int wid  = tid >> 5;
    const int m0   = blockIdx.y * BM;
    const int n0   = blockIdx.x * BN;
    const int wm   = (wid >> 2) * 64;      /* 2 warp rows of 64 */
    const int wn   = (wid & 3)  * 32;      /* 4 warp cols of 32 */

    const int r0 = tid >> 2;               /* 0..63 */
    const int kq = tid & 3;                /* 16B chunk within 32-k row */

    float acc[4][4][4];
#pragma unroll
    for (int i = 0; i < 4; i++)
#pragma unroll
        for (int j = 0; j < 4; j++)
#pragma unroll
            for (int v = 0; v < 4; v++) acc[i][j][v] = 0.f;

    const int nch = K / BK;

    /* issue one 32-k chunk into stage s */
    auto issue = [&](int c, int s) {
        const int kc = c * BK;
        const uint32_t sb = smu + (uint32_t)s * STAGE_BYTES;
#pragma unroll
        for (int i = 0; i < 2; i++) {
            const int r = r0 + 64 * i;
            const uint32_t wo = sm_off(r, kq);
            const size_t ga = (size_t)(m0 + r) * K + kc + kq * 8;
            const size_t gb = (size_t)(n0 + r) * K + kc + kq * 8;
            cp16(sb + ST_A_HI + wo, Ahi + ga);
            cp16(sb + ST_A_LO + wo, Alo + ga);
            cp16(sb + ST_B_HI + wo, Bhi + gb);
            cp16(sb + ST_B_LO + wo, Blo + gb);
        }
        CP_COMMIT();
    };

    issue(0, 0);
    if (nch > 1) issue(1, 1);

    for (int c = 0; c < nch; c++) {
        if (c + 1 < nch) { CP_WAIT(1); } else { CP_WAIT(0); }
        __syncthreads();

        const uint32_t sb = smu + (uint32_t)(c & 1) * STAGE_BYTES;
#pragma unroll
        for (int ks = 0; ks < 2; ks++) {
            uint32_t a[4][4], bh[4][2], bl[4][2];
            /* B fragments: 2 ldmatrix.x4 each for hi/lo (2 n-atoms per ldsm) */
#pragma unroll
            for (int half = 0; half < 2; half++) {
                const int n   = wn + 16*half + ((lane >> 4) << 3) + (lane & 7);
                const int kch = 2*ks + ((lane >> 3) & 1);
                const uint32_t off = sm_off(n, kch);
                uint32_t t4[4];
                ldsm4(t4, sb + ST_B_HI + off);
                bh[2*half][0] = t4[0]; bh[2*half][1] = t4[1];
                bh[2*half+1][0] = t4[2]; bh[2*half+1][1] = t4[3];
                ldsm4(t4, sb + ST_B_LO + off);
                bl[2*half][0] = t4[0]; bl[2*half][1] = t4[1];
                bl[2*half+1][0] = t4[2]; bl[2*half+1][1] = t4[3];
            }
            /* A hi fragments */
#pragma unroll
            for (int am = 0; am < 4; am++) {
                const int row = wm + 16*am + (lane & 15);
                const int kch = 2*ks + (lane >> 4);
                ldsm4(a[am], sb + ST_A_HI + sm_off(row, kch));
            }
#pragma unroll
            for (int am = 0; am < 4; am++)
#pragma unroll
                for (int bn = 0; bn < 4; bn++) {
                    mma16816(acc[am][bn], a[am], bh[bn]);
                    mma16816(acc[am][bn], a[am], bl[bn]);
                }
            /* A lo fragments (reuse regs) */
#pragma unroll
            for (int am = 0; am < 4; am++) {
                const int row = wm + 16*am + (lane & 15);
                const int kch = 2*ks + (lane >> 4);
                ldsm4(a[am], sb + ST_A_LO + sm_off(row, kch));
            }
#pragma unroll
            for (int am = 0; am < 4; am++)
#pragma unroll
                for (int bn = 0; bn < 4; bn++)
                    mma16816(acc[am][bn], a[am], bh[bn]);
        }
        __syncthreads();
        if (c + 2 < nch) issue(c + 2, c & 1);
    }

    /* --------------------------- epilogue ---------------------------------- */
    const int g  = lane >> 2;
    const int t2 = (lane & 3) * 2;
#pragma unroll
    for (int am = 0; am < 4; am++)
#pragma unroll
        for (int bn = 0; bn < 4; bn++) {
            const int n = n0 + wn + 8*bn + t2;
#pragma unroll
            for (int half = 0; half < 2; half++) {
                const int m = m0 + wm + 16*am + g + 8*half;
                const float x0 = acc[am][bn][2*half + 0];
                const float x1 = acc[am][bn][2*half + 1];
                const size_t off = (size_t)m * ldC + n;
                if (EPI == 0) {
                    *(float2*)(C + off) = make_float2(x0, x1);
                } else if (EPI == 1) {
                    *(float2*)(C + off) = make_float2(
                        x0 / (1.f + expf(-x0)), x1 / (1.f + expf(-x1)));
                } else {
                    float2 hv = *(const float2*)(auxH + off);
                    float2 wv = *(const float2*)(auxW + n);
                    float rr = auxR[m];
                    float r0v = hv.x * rr * wv.x / (1.f + expf(-x0));
                    float r1v = hv.y * rr * wv.y / (1.f + expf(-x1));
                    __nv_bfloat16 h0 = __float2bfloat16(r0v);
                    __nv_bfloat16 h1 = __float2bfloat16(r1v);
                    __nv_bfloat162 H, L;
                    H.x = h0; H.y = h1;
                    L.x = __float2bfloat16(r0v - __bfloat162float(h0));
                    L.y = __float2bfloat16(r1v - __bfloat162float(h1));
                    *(__nv_bfloat162*)(Chi + off) = H;
                    *(__nv_bfloat162*)(Clo + off) = L;
                }
            }
        }
}

/* --------------------------- fp32 -> bf16 hi/lo split ----------------------- */
__global__ void __launch_bounds__(256) split_kernel(
    const float4* __restrict__ src, __nv_bfloat162* __restrict__ hi,
    __nv_bfloat162* __restrict__ lo, int n4)
{
    int i = blockIdx.x * blockDim.x + threadIdx.x;
    if (i >= n4) return;
    float4 v = src[i];
    __nv_bfloat16 h0 = __float2bfloat16(v.x), h1 = __float2bfloat16(v.y);
    __nv_bfloat16 h2 = __float2bfloat16(v.z), h3 = __float2bfloat16(v.w);
    __nv_bfloat162 H0, H1, L0, L1;
    H0.x = h0; H0.y = h1; H1.x = h2; H1.y = h3;
    L0.x = __float2bfloat16(v.x - __bfloat162float(h0));
    L0.y = __float2bfloat16(v.y - __bfloat162float(h1));
    L1.x = __float2bfloat16(v.z - __bfloat162float(h2));
    L1.y = __float2bfloat16(v.w - __bfloat162float(h3));
    hi[2*i] = H0; hi[2*i+1] = H1;
    lo[2*i] = L0; lo[2*i+1] = L1;
}

/* ----------------- attention A: per-block KV outer-product sums ------------ */
__global__ void __launch_bounds__(256) attn_kvsum_kernel(
    const float* __restrict__ qkv, float* __restrict__ S)
{
    const int blk = blockIdx.x, h = blockIdx.y;
    __shared__ float Ks[64][65];
    __shared__ float Vs[64][65];
    __shared__ float tab[257];

    const int tid = threadIdx.x;
    const float slope = head_slope(h);
    for (int i = tid; i < 257; i += 256) tab[i] = expf(-slope * (float)i);

    const int tx = tid & 15, ty = tid >> 4;
    float acc[4][4];
#pragma unroll
    for (int i = 0; i < 4; i++)
#pragma unroll
        for (int j = 0; j < 4; j++) acc[i][j] = 0.f;

    for (int nc = 0; nc < 4; nc++) {
        __syncthreads();
        for (int idx = tid; idx < 1024; idx += 256) {
            int n  = idx >> 4;
            int d4 = (idx & 15) << 2;
            int ng = nc*64 + n;
            const float* base = qkv + (size_t)(blk*256 + ng) * QKVW + h*192;
            float4 k4 = *(const float4*)(base + 64 + d4);
            float  kd = tab[255 - ng];
            Ks[n][d4+0] = k4.x*kd; Ks[n][d4+1] = k4.y*kd;
            Ks[n][d4+2] = k4.z*kd; Ks[n][d4+3] = k4.w*kd;
            float4 v4 = *(const float4*)(base + 128 + d4);
            Vs[n][d4+0] = v4.x; Vs[n][d4+1] = v4.y;
            Vs[n][d4+2] = v4.z; Vs[n][d4+3] = v4.w;
        }
        __syncthreads();
#pragma unroll 8
        for (int n = 0; n < 64; n++) {
            float a[4], b[4];
#pragma unroll
            for (int i = 0; i < 4; i++) a[i] = Ks[n][ty*4 + i];
#pragma unroll
            for (int j = 0; j < 4; j++) b[j] = Vs[n][tx*4 + j];
#pragma unroll
            for (int i = 0; i < 4; i++)
#pragma unroll
                for (int j = 0; j < 4; j++) acc[i][j] += a[i]*b[j];
        }
    }
    float* sp = S + ((size_t)h*NB + blk)*4096;
#pragma unroll
    for (int i = 0; i < 4; i++)
        *(float4*)(sp + (ty*4 + i)*64 + tx*4) =
            make_float4(acc[i][0], acc[i][1], acc[i][2], acc[i][3]);
}

/* ---------------- attention B: scan of KV states across blocks ------------- */
__global__ void __launch_bounds__(256) attn_scan_kernel(
    const float* __restrict__ S, const float* __restrict__ kv0,
    float* __restrict__ KV)
{
    const int h = blockIdx.x, tid = threadIdx.x;
    const float bd = expf(-head_slope(h) * 256.f);
    float kv[16];
#pragma unroll
    for (int i = 0; i < 16; i++) kv[i] = kv0[(size_t)h*4096 + tid + i*256];
    for (int j = 0; j < NB; j++) {
        size_t base = ((size_t)h*NB + j)*4096;
#pragma unroll
        for (int i = 0; i < 16; i++) {
            KV[base + tid + i*256] = kv[i];
            kv[i] = bd*kv[i] + S[base + tid + i*256];
        }
    }
}

/* -------- attention C: per (head, block) output tile (inter + intra) ------- */
/* 512 threads: 64 row-groups of 4 rows (ty), 8 col-groups of 8 cols (tx).    */
#define ATTN_SMEM_FLOATS (288 + 2*256*65 + 3*64*65)
#define ATTN_SMEM_BYTES  (ATTN_SMEM_FLOATS * 4)

__global__ void __launch_bounds__(512) attn_out_kernel(
    const float* __restrict__ qkv, const float* __restrict__ KV,
    float* __restrict__ hid)
{
    extern __shared__ float sm[];
    float* tab = sm;
    float* Qs  = sm + 288;
    float* Ps  = Qs + 256*65;
    float* Ks  = Ps + 256*65;
    float* Vs  = Ks + 64*65;
    float* KVs = Vs + 64*65;

    const int blk = blockIdx.x, h = blockIdx.y;
    const int tid = threadIdx.x;
    const float slope = head_slope(h);
    for (int i = tid; i < 257; i += 512) tab[i] = expf(-slope * (float)i);

    for (int idx = tid; idx < 4096; idx += 512) {
        int m = idx >> 4, d4 = (idx & 15) << 2;
        float4 q4 = *(const float4*)(qkv + (size_t)(blk*256 + m)*QKVW + h*192 + d4);
        float* qp = Qs + m*65 + d4;
        qp[0] = q4.x; qp[1] = q4.y; qp[2] = q4.z; qp[3] = q4.w;
    }
    for (int idx = tid; idx < 1024; idx += 512) {
        int d = idx >> 4, e4 = (idx & 15) << 2;
        float4 v4 = *(const float4*)(KV + ((size_t)h*NB + blk)*4096 + d*64 + e4);
        float* kp = KVs + d*65 + e4;
        kp[0] = v4.x; kp[1] = v4.y; kp[2] = v4.z; kp[3] = v4.w;
    }
    __syncthreads();

    const int tx = tid & 7;        /* 8 col groups (8 cols each)  */
    const int ty = tid >> 3;       /* 64 row groups (4 rows each) */
    const int m0 = ty * 4;
    /* warp covers rows [16*warp, 16*warp+15] — warp-uniform bound */
    const int wrow_hi = ((tid >> 5) << 4) + 15;

    float acc[4][8];
#pragma unroll
    for (int i = 0; i < 4; i++)
#pragma unroll
        for (int j = 0; j < 8; j++) acc[i][j] = 0.f;

    /* inter: (Q .* q_decay) @ KV */
#pragma unroll 4
    for (int d = 0; d < 64; d++) {
        float a[4], b[8];
#pragma unroll
        for (int i = 0; i < 4; i++) a[i] = Qs[(m0 + i)*65 + d];
#pragma unroll
        for (int j = 0; j < 8; j++) b[j] = KVs[d*65 + tx*8 + j];
#pragma unroll
        for (int i = 0; i < 4; i++)
#pragma unroll
            for (int j = 0; j < 8; j++) acc[i][j] += a[i]*b[j];
    }
#pragma unroll
    for (int i = 0; i < 4; i++) {
        float qd = tab[m0 + i + 1];
#pragma unroll
        for (int j = 0; j < 8; j++) acc[i][j] *= qd;
    }

    for (int nc = 0; nc < 4; nc++) {
        __syncthreads();
        for (int idx = tid; idx < 1024; idx += 512) {
            int n = idx >> 4, d4 = (idx & 15) << 2;
            const float* base = qkv + (size_t)(blk*256 + nc*64 + n)*QKVW + h*192;
            float4 k4 = *(const float4*)(base + 64 + d4);
            Ks[(d4+0)*65 + n] = k4.x; Ks[(d4+1)*65 + n] = k4.y;
            Ks[(d4+2)*65 + n] = k4.z; Ks[(d4+3)*65 + n] = k4.w;
            float4 v4 = *(const float4*)(base + 128 + d4);
            float* vp = Vs + n*65 + d4;
            vp[0] = v4.x; vp[1] = v4.y; vp[2] = v4.z; vp[3] = v4.w;
        }
        __syncthreads();

        if (wrow_hi >= nc*64) {              /* warp-uniform triangular skip */
            float p[4][8];
#pragma unroll
            for (int i = 0; i < 4; i++)
#pragma unroll
                for (int j = 0; j < 8; j++) p[i][j] = 0.f;
#pragma unroll 4
            for (int d = 0; d < 64; d++) {
                float a[4], b[8];
#pragma unroll
                for (int i = 0; i < 4; i++) a[i] = Qs[(m0 + i)*65 + d];
#pragma unroll
                for (int j = 0; j < 8; j++) b[j] = Ks[d*65 + tx*8 + j];
#pragma unroll
                for (int i = 0; i < 4; i++)
#pragma unroll
                    for (int j = 0; j < 8; j++) p[i][j] += a[i]*b[j];
            }
            /* decayed causal mask; Ps rows are private to this warp */
#pragma unroll
            for (int i = 0; i < 4; i++) {
                int mm = m0 + i;
#pragma unroll
                for (int j = 0; j < 8; j++) {
                    int nn = nc*64 + tx*8 + j;
                    int delta = mm - nn;
                    Ps[mm*65 + tx*8 + j] = (delta >= 0) ? p[i][j]*tab[delta] : 0.f;
                }
            }
            __syncwarp();
#pragma unroll 4
            for (int n = 0; n < 64; n++) {
                float a[4], b[8];
#pragma unroll
                for (int i = 0; i < 4; i++) a[i] = Ps[(m0 + i)*65 + n];
#pragma unroll
                for (int j = 0; j < 8; j++) b[j] = Vs[n*65 + tx*8 + j];
#pragma unroll
                for (int i = 0; i < 4; i++)
#pragma unroll
                    for (int j = 0; j < 8; j++) acc[i][j] += a[i]*b[j];
            }
        }
    }

    float* op = hid + (size_t)(blk*256) * HID + h*64;
#pragma unroll
    for (int i = 0; i < 4; i++) {
        float4* dst = (float4*)(op + (size_t)(m0 + i)*HID + tx*8);
        dst[0] = make_float4(acc[i][0], acc[i][1], acc[i][2], acc[i][3]);
        dst[1] = make_float4(acc[i][4], acc[i][5], acc[i][6], acc[i][7]);
    }
}

/* --------------------------- rmsnorm rstd vector --------------------------- */
__global__ void __launch_bounds__(256) rms_kernel(
    const float* __restrict__ hid, float* __restrict__ rstd)
{
    const int row = blockIdx.x, tid = threadIdx.x;
    const float* p = hid + (size_t)row * HID;
    float s = 0.f;
    {
        int i = tid * 8;
        float4 a = *(const float4*)(p + i);
        float4 b = *(const float4*)(p + i + 4);
        s = a.x*a.x + a.y*a.y + a.z*a.z + a.w*a.w
          + b.x*b.x + b.y*b.y + b.z*b.z + b.w*b.w;
    }
#pragma unroll
    for (int off = 16; off; off >>= 1) s += __shfl_xor_sync(~0u, s, off);
    __shared__ float red[8];
    if ((tid & 31) == 0) red[tid >> 5] = s;
    __syncthreads();
    if (tid < 8) {
        float v = red[tid];
#pragma unroll
        for (int off = 4; off; off >>= 1) v += __shfl_xor_sync(0xffu, v, off);
        if (tid == 0) rstd[row] = rsqrtf(v * (1.f / HID) + 1e-5f);
    }
}

/* --------------------------------- launch ---------------------------------- */
extern "C" void kernel_launch(void* const* d_in, const int* in_sizes, int n_in,
                              void* d_out, int out_size)
{
    (void)in_sizes; (void)n_in; (void)out_size;
    const float* hs   = (const float*)d_in[0];
    const float* kv0  = (const float*)d_in[1];
    const float* Wqkv = (const float*)d_in[2];
    const float* Wg   = (const float*)d_in[3];
    const float* Wo   = (const float*)d_in[4];
    const float* nw   = (const float*)d_in[5];
    float* out = (float*)d_out;

    float *qkv, *S, *KV, *hid, *rstd;
    __nv_bfloat16 *hs_hi, *hs_lo, *wq_hi, *wq_lo, *wg_hi, *wg_lo, *wo_hi, *wo_lo;
    __nv_bfloat16 *tmp_hi, *tmp_lo;
    cudaGetSymbolAddress((void**)&qkv,  g_qkv);
    cudaGetSymbolAddress((void**)&S,    g_S);
    cudaGetSymbolAddress((void**)&KV,   g_KV);
    cudaGetSymbolAddress((void**)&hid,  g_hid);
    cudaGetSymbolAddress((void**)&rstd, g_rstd);
    cudaGetSymbolAddress((void**)&hs_hi, g_hs_hi);
    cudaGetSymbolAddress((void**)&hs_lo, g_hs_lo);
    cudaGetSymbolAddress((void**)&wq_hi, g_wqkv_hi);
    cudaGetSymbolAddress((void**)&wq_lo, g_wqkv_lo);
    cudaGetSymbolAddress((void**)&wg_hi, g_wg_hi);
    cudaGetSymbolAddress((void**)&wg_lo, g_wg_lo);
    cudaGetSymbolAddress((void**)&wo_hi, g_wo_hi);
    cudaGetSymbolAddress((void**)&wo_lo, g_wo_lo);
    cudaGetSymbolAddress((void**)&tmp_hi, g_tmp_hi);
    cudaGetSymbolAddress((void**)&tmp_lo, g_tmp_lo);

    cudaFuncSetAttribute(attn_out_kernel,
                         cudaFuncAttributeMaxDynamicSharedMemorySize, ATTN_SMEM_BYTES);
    cudaFuncSetAttribute(mma_gemm_kernel<0>,
                         cudaFuncAttributeMaxDynamicSharedMemorySize, GEMM_SMEM);
    cudaFuncSetAttribute(mma_gemm_kernel<1>,
                         cudaFuncAttributeMaxDynamicSharedMemorySize, GEMM_SMEM);
    cudaFuncSetAttribute(mma_gemm_kernel<2>,
                         cudaFuncAttributeMaxDynamicSharedMemorySize, GEMM_SMEM);

    /* 0. bf16 hi/lo splits */
    split_kernel<<<(NTOK*HID/4 + 255)/256, 256>>>(
        (const float4*)hs, (__nv_bfloat162*)hs_hi, (__nv_bfloat162*)hs_lo, NTOK*HID/4);
    split_kernel<<<(QKVW*HID/4 + 255)/256, 256>>>(
        (const float4*)Wqkv, (__nv_bfloat162*)wq_hi, (__nv_bfloat162*)wq_lo, QKVW*HID/4);
    split_kernel<<<(HID*HID/4 + 255)/256, 256>>>(
        (const float4*)Wg, (__nv_bfloat162*)wg_hi, (__nv_bfloat162*)wg_lo, HID*HID/4);
    split_kernel<<<(HID*HID/4 + 255)/256, 256>>>(
        (const float4*)Wo, (__nv_bfloat162*)wo_hi, (__nv_bfloat162*)wo_lo, HID*HID/4);

    /* 1. qkv = silu(hs @ Wqkv^T) */
    mma_gemm_kernel<1><<<dim3(QKVW/BN, NTOK/BM), 256, GEMM_SMEM>>>(
        hs_hi, hs_lo, wq_hi, wq_lo, HID, QKVW, qkv,
        nullptr, nullptr, nullptr, nullptr, nullptr);

    /* 2-4. lightning attention */
    attn_kvsum_kernel<<<dim3(NB, NH), 256>>>(qkv, S);
    attn_scan_kernel<<<NH, 256>>>(S, kv0, KV);
    attn_out_kernel<<<dim3(NB, NH), 512, ATTN_SMEM_BYTES>>>(qkv, KV, hid);

    /* 5. rmsnorm scale vector */
    rms_kernel<<<NTOK, 256>>>(hid, rstd);

    /* 6. tmp = sigmoid(hs @ Wg^T) * hid * rstd * nw -> bf16 hi/lo */
    mma_gemm_kernel<2><<<dim3(HID/BN, NTOK/BM), 256, GEMM_SMEM>>>(
        hs_hi, hs_lo, wg_hi, wg_lo, HID, HID, nullptr,
        tmp_hi, tmp_lo, hid, rstd, nw);

    /* 7. out = tmp @ Wo^T */
    mma_gemm_kernel<0><<<dim3(HID/BN, NTOK/BM), 256, GEMM_SMEM>>>(
        tmp_hi, tmp_lo, wo_hi, wo_lo, HID, HID, out,
        nullptr, nullptr, nullptr, nullptr, nullptr);
}

// round 7
// speedup vs baseline: 1.3706x; 1.2971x over previous
#include <cuda_runtime.h>
#include <cuda_fp16.h>
#include <math.h>
#include <stdint.h>

#define HID   2048
#define NTOK  8192
#define NH    32
#define HD    64
#define NB    32            /* 8192 / 256 */
#define QKVW  (3*HID)       /* 6144 */

/* ------------- GEMM tiling (mma.sync fp16, A split 2-pass) ----------------- */
#define BM 128
#define BN 128
#define BK 32
#define ST_A_HI 0
#define ST_A_LO 8192
#define ST_B    16384
#define STAGE_BYTES 24576           /* 8+8+8 KB */
#define GEMM_SMEM (2*STAGE_BYTES)   /* 48 KB */

/* ------------------------- scratch (device globals) ------------------------ */
__device__ float g_qkv[(size_t)NTOK * QKVW];
__device__ float g_S  [(size_t)NH * NB * HD * HD];
__device__ float g_KV [(size_t)NH * NB * HD * HD];
__device__ float g_hid[(size_t)NTOK * HID];
__device__ float g_rstd[NTOK];
__device__ __half g_hs_hi [(size_t)NTOK * HID];
__device__ __half g_hs_lo [(size_t)NTOK * HID];
__device__ __half g_wqkv_h[(size_t)QKVW * HID];
__device__ __half g_wg_h  [(size_t)HID * HID];
__device__ __half g_wo_h  [(size_t)HID * HID];
__device__ __half g_tmp_hi[(size_t)NTOK * HID];
__device__ __half g_tmp_lo[(size_t)NTOK * HID];

/* ------------------------------ PTX helpers -------------------------------- */
__device__ __forceinline__ uint32_t smem_u32(const void* p) {
    uint32_t a;
    asm("{ .reg .u64 t; cvta.to.shared.u64 t, %1; cvt.u32.u64 %0, t; }"
        : "=r"(a) : "l"(p));
    return a;
}
__device__ __forceinline__ void cp16(uint32_t dst, const void* src) {
    asm volatile("cp.async.cg.shared.global [%0], [%1], 16;"
                 :: "r"(dst), "l"(src));
}
#define CP_COMMIT()  asm volatile("cp.async.commit_group;" ::: "memory")
#define CP_WAIT(n)   asm volatile("cp.async.wait_group %0;" :: "n"(n) : "memory")

__device__ __forceinline__ void ldsm4(uint32_t* r, uint32_t addr) {
    asm volatile("ldmatrix.sync.aligned.m8n8.x4.shared.b16 {%0,%1,%2,%3}, [%4];"
                 : "=r"(r[0]), "=r"(r[1]), "=r"(r[2]), "=r"(r[3]) : "r"(addr));
}
__device__ __forceinline__ void mma16816(float* d, const uint32_t* a,
                                         const uint32_t* b) {
    asm volatile(
        "mma.sync.aligned.m16n8k16.row.col.f32.f16.f16.f32 "
        "{%0,%1,%2,%3}, {%4,%5,%6,%7}, {%8,%9}, {%0,%1,%2,%3};"
        : "+f"(d[0]), "+f"(d[1]), "+f"(d[2]), "+f"(d[3])
        : "r"(a[0]), "r"(a[1]), "r"(a[2]), "r"(a[3]), "r"(b[0]), "r"(b[1]));
}

__device__ __forceinline__ float head_slope(int h) {
    return exp2f(-0.25f * (float)(h + 1)) * 1.00001f;
}

/* tile-contiguous smem layout: tile(kch, tr) at (kch*16 + tr)*128 bytes,
   within-tile row slot = (row&7) ^ kch (both loads & stores use it).       */
__device__ __forceinline__ uint32_t sm_off(int row, int kch) {
    return ((uint32_t)(kch << 4) + (uint32_t)(row >> 3)) * 128u
         + (uint32_t)(((row & 7) ^ kch) << 4);
}

/* ------------------- mma.sync fp16 2-pass (A-split) GEMM ------------------- */
/* C[m,n] = epi( sum_k A[m,k]*B[n,k] ), A=[M,K] fp16 hi/lo pair, B=[N,K] fp16.
   EPI 0: C fp32.  EPI 1: silu -> C fp32.
   EPI 2: sigmoid(x)*auxH[m,n]*auxR[m]*auxW[n] -> split into Chi/Clo fp16.   */
template<int EPI>
__global__ void __launch_bounds__(256, 2) mma_gemm_kernel(
    const __half* __restrict__ Ahi, const __half* __restrict__ Alo,
    const __half* __restrict__ Bh,
    int K, int ldC,
    float* __restrict__ C,
    __half* __restrict__ Chi, __half* __restrict__ Clo,
    const float* __restrict__ auxH, const float* __restrict__ auxR,
    const float* __restrict__ auxW)
{
    extern __shared__ char smraw[];
    const uint32_t smu = smem_u32(smraw);
    const int tid  = threadIdx.x;
    const int lane = tid & 31;
    const int wid  = tid >> 5;
    const int m0   = blockIdx.y * BM;
    const int n0   = blockIdx.x * BN;
    const int wm   = (wid >> 2) * 64;      /* 2 warp rows of 64 */
    const int wn   = (wid & 3)  * 32;      /* 4 warp cols of 32 */

    const int r0 = tid >> 2;               /* 0..63 */
    const int kq = tid & 3;                /* 16B chunk within 32-k row */

    float acc[4][4][4];
#pragma unroll
    for (int i = 0; i < 4; i++)
#pragma unroll
        for (int j = 0; j < 4; j++)
#pragma unroll
            for (int v = 0; v < 4; v++) acc[i][j][v] = 0.f;

    const int nch = K / BK;

    /* issue one 32-k chunk into stage s */
    auto issue = [&](int c, int s) {
        const int kc = c * BK;
        const uint32_t sb = smu + (uint32_t)s * STAGE_BYTES;
#pragma unroll
        for (int i = 0; i < 2; i++) {
            const int r = r0 + 64 * i;
            const uint32_t wo = sm_off(r, kq);
            const size_t ga = (size_t)(m0 + r) * K + kc + kq * 8;
            const size_t gb = (size_t)(n0 + r) * K + kc + kq * 8;
            cp16(sb + ST_A_HI + wo, Ahi + ga);
            cp16(sb + ST_A_LO + wo, Alo + ga);
            cp16(sb + ST_B    + wo, Bh  + gb);
        }
        CP_COMMIT();
    };

    issue(0, 0);
    if (nch > 1) issue(1, 1);

    for (int c = 0; c < nch; c++) {
        if (c + 1 < nch) { CP_WAIT(1); } else { CP_WAIT(0); }
        __syncthreads();

        const uint32_t sb = smu + (uint32_t)(c & 1) * STAGE_BYTES;
#pragma unroll
        for (int ks = 0; ks < 2; ks++) {
            uint32_t a[4][4], bh[4][2];
            /* B fragments: 2 ldmatrix.x4 (2 n-atoms per ldsm) */
#pragma unroll
            for (int half = 0; half < 2; half++) {
                const int n   = wn + 16*half + ((lane >> 4) << 3) + (lane & 7);
                const int kch = 2*ks + ((lane >> 3) & 1);
                uint32_t t4[4];
                ldsm4(t4, sb + ST_B + sm_off(n, kch));
                bh[2*half][0] = t4[0]; bh[2*half][1] = t4[1];
                bh[2*half+1][0] = t4[2]; bh[2*half+1][1] = t4[3];
            }
            /* A hi fragments */
#pragma unroll
            for (int am = 0; am < 4; am++) {
                const int row = wm + 16*am + (lane & 15);
                const int kch = 2*ks + (lane >> 4);
                ldsm4(a[am], sb + ST_A_HI + sm_off(row, kch));
            }
#pragma unroll
            for (int am = 0; am < 4; am++)
#pragma unroll
                for (int bn = 0; bn < 4; bn++)
                    mma16816(acc[am][bn], a[am], bh[bn]);
            /* A lo fragments (reuse regs) */
#pragma unroll
            for (int am = 0; am < 4; am++) {
                const int row = wm + 16*am + (lane & 15);
                const int kch = 2*ks + (lane >> 4);
                ldsm4(a[am], sb + ST_A_LO + sm_off(row, kch));
            }
#pragma unroll
            for (int am = 0; am < 4; am++)
#pragma unroll
                for (int bn = 0; bn < 4; bn++)
                    mma16816(acc[am][bn], a[am], bh[bn]);
        }
        __syncthreads();
        if (c + 2 < nch) issue(c + 2, c & 1);
    }

    /* --------------------------- epilogue ---------------------------------- */
    const int g  = lane >> 2;
    const int t2 = (lane & 3) * 2;
#pragma unroll
    for (int am = 0; am < 4; am++)
#pragma unroll
        for (int bn = 0; bn < 4; bn++) {
            const int n = n0 + wn + 8*bn + t2;
#pragma unroll
            for (int half = 0; half < 2; half++) {
                const int m = m0 + wm + 16*am + g + 8*half;
                const float x0 = acc[am][bn][2*half + 0];
                const float x1 = acc[am][bn][2*half + 1];
                const size_t off = (size_t)m * ldC + n;
                if (EPI == 0) {
                    *(float2*)(C + off) = make_float2(x0, x1);
                } else if (EPI == 1) {
                    *(float2*)(C + off) = make_float2(
                        x0 / (1.f + expf(-x0)), x1 / (1.f + expf(-x1)));
                } else {
                    float2 hv = *(const float2*)(auxH + off);
                    float2 wv = *(const float2*)(auxW + n);
                    float rr = auxR[m];
                    float r0v = hv.x * rr * wv.x / (1.f + expf(-x0));
                    float r1v = hv.y * rr * wv.y / (1.f + expf(-x1));
                    __half h0 = __float2half_rn(r0v);
                    __half h1 = __float2half_rn(r1v);
                    __half l0 = __float2half_rn(r0v - __half2float(h0));
                    __half l1 = __float2half_rn(r1v - __half2float(h1));
                    *(__half2*)(Chi + off) = __halves2half2(h0, h1);
                    *(__half2*)(Clo + off) = __halves2half2(l0, l1);
                }
            }
        }
}

/* ---------------------- fp32 -> fp16 hi/lo split ---------------------------- */
__global__ void __launch_bounds__(256) split2_kernel(
    const float4* __restrict__ src, __half2* __restrict__ hi,
    __half2* __restrict__ lo, int n4)
{
    int i = blockIdx.x * blockDim.x + threadIdx.x;
    if (i >= n4) return;
    float4 v = src[i];
    __half h0 = __float2half_rn(v.x), h1 = __float2half_rn(v.y);
    __half h2 = __float2half_rn(v.z), h3 = __float2half_rn(v.w);
    hi[2*i]   = __halves2half2(h0, h1);
    hi[2*i+1] = __halves2half2(h2, h3);
    lo[2*i]   = __halves2half2(__float2half_rn(v.x - __half2float(h0)),
                               __float2half_rn(v.y - __half2float(h1)));
    lo[2*i+1] = __halves2half2(__float2half_rn(v.z - __half2float(h2)),
                               __float2half_rn(v.w - __half2float(h3)));
}

/* ---------------------- fp32 -> fp16 plain convert -------------------------- */
__global__ void __launch_bounds__(256) conv1_kernel(
    const float4* __restrict__ src, __half2* __restrict__ hi, int n4)
{
    int i = blockIdx.x * blockDim.x + threadIdx.x;
    if (i >= n4) return;
    float4 v = src[i];
    hi[2*i]   = __halves2half2(__float2half_rn(v.x), __float2half_rn(v.y));
    hi[2*i+1] = __halves2half2(__float2half_rn(v.z), __float2half_rn(v.w));
}

/* ----------------- attention A: per-block KV outer-product sums ------------ */
__global__ void __launch_bounds__(256) attn_kvsum_kernel(
    const float* __restrict__ qkv, float* __restrict__ S)
{
    const int blk = blockIdx.x, h = blockIdx.y;
    __shared__ float Ks[64][65];
    __shared__ float Vs[64][65];
    __shared__ float tab[257];

    const int tid = threadIdx.x;
    const float slope = head_slope(h);
    for (int i = tid; i < 257; i += 256) tab[i] = expf(-slope * (float)i);

    const int tx = tid & 15, ty = tid >> 4;
    float acc[4][4];
#pragma unroll
    for (int i = 0; i < 4; i++)
#pragma unroll
        for (int j = 0; j < 4; j++) acc[i][j] = 0.f;

    for (int nc = 0; nc < 4; nc++) {
        __syncthreads();
        for (int idx = tid; idx < 1024; idx += 256) {
            int n  = idx >> 4;
            int d4 = (idx & 15) << 2;
            int ng = nc*64 + n;
            const float* base = qkv + (size_t)(blk*256 + ng) * QKVW + h*192;
            float4 k4 = *(const float4*)(base + 64 + d4);
            float  kd = tab[255 - ng];
            Ks[n][d4+0] = k4.x*kd; Ks[n][d4+1] = k4.y*kd;
            Ks[n][d4+2] = k4.z*kd; Ks[n][d4+3] = k4.w*kd;
            float4 v4 = *(const float4*)(base + 128 + d4);
            Vs[n][d4+0] = v4.x; Vs[n][d4+1] = v4.y;
            Vs[n][d4+2] = v4.z; Vs[n][d4+3] = v4.w;
        }
        __syncthreads();
#pragma unroll 8
        for (int n = 0; n < 64; n++) {
            float a[4], b[4];
#pragma unroll
            for (int i = 0; i < 4; i++) a[i] = Ks[n][ty*4 + i];
#pragma unroll
            for (int j = 0; j < 4; j++) b[j] = Vs[n][tx*4 + j];
#pragma unroll
            for (int i = 0; i < 4; i++)
#pragma unroll
                for (int j = 0; j < 4; j++) acc[i][j] += a[i]*b[j];
        }
    }
    float* sp = S + ((size_t)h*NB + blk)*4096;
#pragma unroll
    for (int i = 0; i < 4; i++)
        *(float4*)(sp + (ty*4 + i)*64 + tx*4) =
            make_float4(acc[i][0], acc[i][1], acc[i][2], acc[i][3]);
}

/* ---------------- attention B: scan of KV states across blocks ------------- */
__global__ void __launch_bounds__(256) attn_scan_kernel(
    const float* __restrict__ S, const float* __restrict__ kv0,
    float* __restrict__ KV)
{
    const int h = blockIdx.x, tid = threadIdx.x;
    const float bd = expf(-head_slope(h) * 256.f);
    float kv[16];
#pragma unroll
    for (int i = 0; i < 16; i++) kv[i] = kv0[(size_t)h*4096 + tid + i*256];
    for (int j = 0; j < NB; j++) {
        size_t base = ((size_t)h*NB + j)*4096;
#pragma unroll
        for (int i = 0; i < 16; i++) {
            KV[base + tid + i*256] = kv[i];
            kv[i] = bd*kv[i] + S[base + tid + i*256];
        }
    }
}

/* -------- attention C: per (head, block) output tile (inter + intra) ------- */
/* 512 threads: 64 row-groups of 4 rows (ty), 8 col-groups of 8 cols (tx).    */
#define ATTN_SMEM_FLOATS (288 + 2*256*65 + 3*64*65)
#define ATTN_SMEM_BYTES  (ATTN_SMEM_FLOATS * 4)

__global__ void __launch_bounds__(512) attn_out_kernel(
    const float* __restrict__ qkv, const float* __restrict__ KV,
    float* __restrict__ hid)
{
    extern __shared__ float sm[];
    float* tab = sm;
    float* Qs  = sm + 288;
    float* Ps  = Qs + 256*65;
    float* Ks  = Ps + 256*65;
    float* Vs  = Ks + 64*65;
    float* KVs = Vs + 64*65;

    const int blk = blockIdx.x, h = blockIdx.y;
    const int tid = threadIdx.x;
    const float slope = head_slope(h);
    for (int i = tid; i < 257; i += 512) tab[i] = expf(-slope * (float)i);

    for (int idx = tid; idx < 4096; idx += 512) {
        int m = idx >> 4, d4 = (idx & 15) << 2;
        float4 q4 = *(const float4*)(qkv + (size_t)(blk*256 + m)*QKVW + h*192 + d4);
        float* qp = Qs + m*65 + d4;
        qp[0] = q4.x; qp[1] = q4.y; qp[2] = q4.z; qp[3] = q4.w;
    }
    for (int idx = tid; idx < 1024; idx += 512) {
        int d = idx >> 4, e4 = (idx & 15) << 2;
        float4 v4 = *(const float4*)(KV + ((size_t)h*NB + blk)*4096 + d*64 + e4);
        float* kp = KVs + d*65 + e4;
        kp[0] = v4.x; kp[1] = v4.y; kp[2] = v4.z; kp[3] = v4.w;
    }
    __syncthreads();

    const int tx = tid & 7;
    const int ty = tid >> 3;
    const int m0 = ty * 4;
    const int wrow_hi = ((tid >> 5) << 4) + 15;

    float acc[4][8];
#pragma unroll
    for (int i = 0; i < 4; i++)
#pragma unroll
        for (int j = 0; j < 8; j++) acc[i][j] = 0.f;

#pragma unroll 4
    for (int d = 0; d < 64; d++) {
        float a[4], b[8];
#pragma unroll
        for (int i = 0; i < 4; i++) a[i] = Qs[(m0 + i)*65 + d];
#pragma unroll
        for (int j = 0; j < 8; j++) b[j] = KVs[d*65 + tx*8 + j];
#pragma unroll
        for (int i = 0; i < 4; i++)
#pragma unroll
            for (int j = 0; j < 8; j++) acc[i][j] += a[i]*b[j];
    }
#pragma unroll
    for (int i = 0; i < 4; i++) {
        float qd = tab[m0 + i + 1];
#pragma unroll
        for (int j = 0; j < 8; j++) acc[i][j] *= qd;
    }

    for (int nc = 0; nc < 4; nc++) {
        __syncthreads();
        for (int idx = tid; idx < 1024; idx += 512) {
            int n = idx >> 4, d4 = (idx & 15) << 2;
            const float* base = qkv + (size_t)(blk*256 + nc*64 + n)*QKVW + h*192;
            float4 k4 = *(const float4*)(base + 64 + d4);
            Ks[(d4+0)*65 + n] = k4.x; Ks[(d4+1)*65 + n] = k4.y;
            Ks[(d4+2)*65 + n] = k4.z; Ks[(d4+3)*65 + n] = k4.w;
            float4 v4 = *(const float4*)(base + 128 + d4);
            float* vp = Vs + n*65 + d4;
            vp[0] = v4.x; vp[1] = v4.y; vp[2] = v4.z; vp[3] = v4.w;
        }
        __syncthreads();

        if (wrow_hi >= nc*64) {              /* warp-uniform triangular skip */
            float p[4][8];
#pragma unroll
            for (int i = 0; i < 4; i++)
#pragma unroll
                for (int j = 0; j < 8; j++) p[i][j] = 0.f;
#pragma unroll 4
            for (int d = 0; d < 64; d++) {
                float a[4], b[8];
#pragma unroll
                for (int i = 0; i < 4; i++) a[i] = Qs[(m0 + i)*65 + d];
#pragma unroll
                for (int j = 0; j < 8; j++) b[j] = Ks[d*65 + tx*8 + j];
#pragma unroll
                for (int i = 0; i < 4; i++)
#pragma unroll
                    for (int j = 0; j < 8; j++) p[i][j] += a[i]*b[j];
            }
#pragma unroll
            for (int i = 0; i < 4; i++) {
                int mm = m0 + i;
#pragma unroll
                for (int j = 0; j < 8; j++) {
                    int nn = nc*64 + tx*8 + j;
                    int delta = mm - nn;
                    Ps[mm*65 + tx*8 + j] = (delta >= 0) ? p[i][j]*tab[delta] : 0.f;
                }
            }
            __syncwarp();
#pragma unroll 4
            for (int n = 0; n < 64; n++) {
                float a[4], b[8];
#pragma unroll
                for (int i = 0; i < 4; i++) a[i] = Ps[(m0 + i)*65 + n];
#pragma unroll
                for (int j = 0; j < 8; j++) b[j] = Vs[n*65 + tx*8 + j];
#pragma unroll
                for (int i = 0; i < 4; i++)
#pragma unroll
                    for (int j = 0; j < 8; j++) acc[i][j] += a[i]*b[j];
            }
        }
    }

    float* op = hid + (size_t)(blk*256) * HID + h*64;
#pragma unroll
    for (int i = 0; i < 4; i++) {
        float4* dst = (float4*)(op + (size_t)(m0 + i)*HID + tx*8);
        dst[0] = make_float4(acc[i][0], acc[i][1], acc[i][2], acc[i][3]);
        dst[1] = make_float4(acc[i][4], acc[i][5], acc[i][6], acc[i][7]);
    }
}

/* --------------------------- rmsnorm rstd vector --------------------------- */
__global__ void __launch_bounds__(256) rms_kernel(
    const float* __restrict__ hid, float* __restrict__ rstd)
{
    const int row = blockIdx.x, tid = threadIdx.x;
    const float* p = hid + (size_t)row * HID;
    float s = 0.f;
    {
        int i = tid * 8;
        float4 a = *(const float4*)(p + i);
        float4 b = *(const float4*)(p + i + 4);
        s = a.x*a.x + a.y*a.y + a.z*a.z + a.w*a.w
          + b.x*b.x + b.y*b.y + b.z*b.z + b.w*b.w;
    }
#pragma unroll
    for (int off = 16; off; off >>= 1) s += __shfl_xor_sync(~0u, s, off);
    __shared__ float red[8];
    if ((tid & 31) == 0) red[tid >> 5] = s;
    __syncthreads();
    if (tid < 8) {
        float v = red[tid];
#pragma unroll
        for (int off = 4; off; off >>= 1) v += __shfl_xor_sync(0xffu, v, off);
        if (tid == 0) rstd[row] = rsqrtf(v * (1.f / HID) + 1e-5f);
    }
}

/* --------------------------------- launch ---------------------------------- */
extern "C" void kernel_launch(void* const* d_in, const int* in_sizes, int n_in,
                              void* d_out, int out_size)
{
    (void)in_sizes; (void)n_in; (void)out_size;
    const float* hs   = (const float*)d_in[0];
    const float* kv0  = (const float*)d_in[1];
    const float* Wqkv = (const float*)d_in[2];
    const float* Wg   = (const float*)d_in[3];
    const float* Wo   = (const float*)d_in[4];
    const float* nw   = (const float*)d_in[5];
    float* out = (float*)d_out;

    float *qkv, *S, *KV, *hid, *rstd;
    __half *hs_hi, *hs_lo, *wq_h, *wg_h, *wo_h, *tmp_hi, *tmp_lo;
    cudaGetSymbolAddress((void**)&qkv,  g_qkv);
    cudaGetSymbolAddress((void**)&S,    g_S);
    cudaGetSymbolAddress((void**)&KV,   g_KV);
    cudaGetSymbolAddress((void**)&hid,  g_hid);
    cudaGetSymbolAddress((void**)&rstd, g_rstd);
    cudaGetSymbolAddress((void**)&hs_hi, g_hs_hi);
    cudaGetSymbolAddress((void**)&hs_lo, g_hs_lo);
    cudaGetSymbolAddress((void**)&wq_h, g_wqkv_h);
    cudaGetSymbolAddress((void**)&wg_h, g_wg_h);
    cudaGetSymbolAddress((void**)&wo_h, g_wo_h);
    cudaGetSymbolAddress((void**)&tmp_hi, g_tmp_hi);
    cudaGetSymbolAddress((void**)&tmp_lo, g_tmp_lo);

    cudaFuncSetAttribute(attn_out_kernel,
                         cudaFuncAttributeMaxDynamicSharedMemorySize, ATTN_SMEM_BYTES);
    cudaFuncSetAttribute(mma_gemm_kernel<0>,
                         cudaFuncAttributeMaxDynamicSharedMemorySize, GEMM_SMEM);
    cudaFuncSetAttribute(mma_gemm_kernel<1>,
                         cudaFuncAttributeMaxDynamicSharedMemorySize, GEMM_SMEM);
    cudaFuncSetAttribute(mma_gemm_kernel<2>,
                         cudaFuncAttributeMaxDynamicSharedMemorySize, GEMM_SMEM);

    /* 0. fp16 conversions: hs -> hi/lo split, weights -> single fp16 */
    split2_kernel<<<(NTOK*HID/4 + 255)/256, 256>>>(
        (const float4*)hs, (__half2*)hs_hi, (__half2*)hs_lo, NTOK*HID/4);
    conv1_kernel<<<(QKVW*HID/4 + 255)/256, 256>>>(
        (const float4*)Wqkv, (__half2*)wq_h, QKVW*HID/4);
    conv1_kernel<<<(HID*HID/4 + 255)/256, 256>>>(
        (const float4*)Wg, (__half2*)wg_h, HID*HID/4);
    conv1_kernel<<<(HID*HID/4 + 255)/256, 256>>>(
        (const float4*)Wo, (__half2*)wo_h, HID*HID/4);

    /* 1. qkv = silu(hs @ Wqkv^T) */
    mma_gemm_kernel<1><<<dim3(QKVW/BN, NTOK/BM), 256, GEMM_SMEM>>>(
        hs_hi, hs_lo, wq_h, HID, QKVW, qkv,
        nullptr, nullptr, nullptr, nullptr, nullptr);

    /* 2-4. lightning attention */
    attn_kvsum_kernel<<<dim3(NB, NH), 256>>>(qkv, S);
    attn_scan_kernel<<<NH, 256>>>(S, kv0, KV);
    attn_out_kernel<<<dim3(NB, NH), 512, ATTN_SMEM_BYTES>>>(qkv, KV, hid);

    /* 5. rmsnorm scale vector */
    rms_kernel<<<NTOK, 256>>>(hid, rstd);

    /* 6. tmp = sigmoid(hs @ Wg^T) * hid * rstd * nw -> fp16 hi/lo */
    mma_gemm_kernel<2><<<dim3(HID/BN, NTOK/BM), 256, GEMM_SMEM>>>(
        hs_hi, hs_lo, wg_h, HID, HID, nullptr,
        tmp_hi, tmp_lo, hid, rstd, nw);

    /* 7. out = tmp @ Wo^T */
    mma_gemm_kernel<0><<<dim3(HID/BN, NTOK/BM), 256, GEMM_SMEM>>>(
        tmp_hi, tmp_lo, wo_h, HID, HID, out,
        nullptr, nullptr, nullptr, nullptr, nullptr);
}

// round 8
// speedup vs baseline: 1.9703x; 1.4376x over previous
#include <cuda_runtime.h>
#include <cuda_fp16.h>
#include <math.h>
#include <stdint.h>

#define HID   2048
#define NTOK  8192
#define NH    32
#define HD    64
#define NB    32            /* 8192 / 256 */
#define QKVW  (3*HID)       /* 6144 */

/* ---------------- GEMM tiling (mma.sync fp16, single pass) ----------------- */
#define BM 128
#define BN 128
#define BK 32
#define ST_A 0
#define ST_B 8192
#define STAGE_BYTES 16384           /* 8+8 KB */
#define GEMM_SMEM (2*STAGE_BYTES)   /* 32 KB */

/* ------------------------- scratch (device globals) ------------------------ */
__device__ float g_qkv[(size_t)NTOK * QKVW];
__device__ float g_S  [(size_t)NH * NB * HD * HD];
__device__ float g_KV [(size_t)NH * NB * HD * HD];
__device__ float g_hid[(size_t)NTOK * HID];
__device__ float g_rstd[NTOK];
__device__ __half g_hs_h  [(size_t)NTOK * HID];
__device__ __half g_wqkv_h[(size_t)QKVW * HID];
__device__ __half g_wg_h  [(size_t)HID * HID];
__device__ __half g_wo_h  [(size_t)HID * HID];
__device__ __half g_tmp_h [(size_t)NTOK * HID];

/* ------------------------------ PTX helpers -------------------------------- */
__device__ __forceinline__ uint32_t smem_u32(const void* p) {
    uint32_t a;
    asm("{ .reg .u64 t; cvta.to.shared.u64 t, %1; cvt.u32.u64 %0, t; }"
        : "=r"(a) : "l"(p));
    return a;
}
__device__ __forceinline__ void cp16(uint32_t dst, const void* src) {
    asm volatile("cp.async.cg.shared.global [%0], [%1], 16;"
                 :: "r"(dst), "l"(src));
}
#define CP_COMMIT()  asm volatile("cp.async.commit_group;" ::: "memory")
#define CP_WAIT(n)   asm volatile("cp.async.wait_group %0;" :: "n"(n) : "memory")

__device__ __forceinline__ void ldsm4(uint32_t* r, uint32_t addr) {
    asm volatile("ldmatrix.sync.aligned.m8n8.x4.shared.b16 {%0,%1,%2,%3}, [%4];"
                 : "=r"(r[0]), "=r"(r[1]), "=r"(r[2]), "=r"(r[3]) : "r"(addr));
}
__device__ __forceinline__ void mma16816(float* d, const uint32_t* a,
                                         const uint32_t* b) {
    asm volatile(
        "mma.sync.aligned.m16n8k16.row.col.f32.f16.f16.f32 "
        "{%0,%1,%2,%3}, {%4,%5,%6,%7}, {%8,%9}, {%0,%1,%2,%3};"
        : "+f"(d[0]), "+f"(d[1]), "+f"(d[2]), "+f"(d[3])
        : "r"(a[0]), "r"(a[1]), "r"(a[2]), "r"(a[3]), "r"(b[0]), "r"(b[1]));
}

__device__ __forceinline__ float head_slope(int h) {
    return exp2f(-0.25f * (float)(h + 1)) * 1.00001f;
}

/* tile-contiguous smem layout: tile(kch, tr) at (kch*16 + tr)*128 bytes,
   within-tile row slot = (row&7) ^ kch (both loads & stores use it).       */
__device__ __forceinline__ uint32_t sm_off(int row, int kch) {
    return ((uint32_t)(kch << 4) + (uint32_t)(row >> 3)) * 128u
         + (uint32_t)(((row & 7) ^ kch) << 4);
}

/* ---------------------- mma.sync fp16 single-pass GEMM --------------------- */
/* C[m,n] = epi( sum_k A[m,k]*B[n,k] ), A=[M,K] fp16, B=[N,K] fp16.
   EPI 0: C fp32.  EPI 1: silu -> C fp32.
   EPI 2: sigmoid(x)*auxH[m,n]*auxR[m]*auxW[n] -> Chalf fp16.                */
template<int EPI>
__global__ void __launch_bounds__(256, 2) mma_gemm_kernel(
    const __half* __restrict__ Ah, const __half* __restrict__ Bh,
    int K, int ldC,
    float* __restrict__ C, __half* __restrict__ Chalf,
    const float* __restrict__ auxH, const float* __restrict__ auxR,
    const float* __restrict__ auxW)
{
    extern __shared__ char smraw[];
    const uint32_t smu = smem_u32(smraw);
    const int tid  = threadIdx.x;
    const int lane = tid & 31;
    const int wid  = tid >> 5;
    const int m0   = blockIdx.y * BM;
    const int n0   = blockIdx.x * BN;
    const int wm   = (wid >> 2) * 64;      /* 2 warp rows of 64 */
    const int wn   = (wid & 3)  * 32;      /* 4 warp cols of 32 */

    const int r0 = tid >> 2;               /* 0..63 */
    const int kq = tid & 3;                /* 16B chunk within 32-k row */

    float acc[4][4][4];
#pragma unroll
    for (int i = 0; i < 4; i++)
#pragma unroll
        for (int j = 0; j < 4; j++)
#pragma unroll
            for (int v = 0; v < 4; v++) acc[i][j][v] = 0.f;

    const int nch = K / BK;

    /* issue one 32-k chunk into stage s */
    auto issue = [&](int c, int s) {
        const int kc = c * BK;
        const uint32_t sb = smu + (uint32_t)s * STAGE_BYTES;
#pragma unroll
        for (int i = 0; i < 2; i++) {
            const int r = r0 + 64 * i;
            const uint32_t wo = sm_off(r, kq);
            const size_t ga = (size_t)(m0 + r) * K + kc + kq * 8;
            const size_t gb = (size_t)(n0 + r) * K + kc + kq * 8;
            cp16(sb + ST_A + wo, Ah + ga);
            cp16(sb + ST_B + wo, Bh + gb);
        }
        CP_COMMIT();
    };

    issue(0, 0);
    if (nch > 1) issue(1, 1);

    for (int c = 0; c < nch; c++) {
        if (c + 1 < nch) { CP_WAIT(1); } else { CP_WAIT(0); }
        __syncthreads();

        const uint32_t sb = smu + (uint32_t)(c & 1) * STAGE_BYTES;
#pragma unroll
        for (int ks = 0; ks < 2; ks++) {
            uint32_t a[4][4], bh[4][2];
            /* B fragments: 2 ldmatrix.x4 (2 n-atoms per ldsm) */
#pragma unroll
            for (int half = 0; half < 2; half++) {
                const int n   = wn + 16*half + ((lane >> 4) << 3) + (lane & 7);
                const int kch = 2*ks + ((lane >> 3) & 1);
                uint32_t t4[4];
                ldsm4(t4, sb + ST_B + sm_off(n, kch));
                bh[2*half][0] = t4[0]; bh[2*half][1] = t4[1];
                bh[2*half+1][0] = t4[2]; bh[2*half+1][1] = t4[3];
            }
            /* A fragments */
#pragma unroll
            for (int am = 0; am < 4; am++) {
                const int row = wm + 16*am + (lane & 15);
                const int kch = 2*ks + (lane >> 4);
                ldsm4(a[am], sb + ST_A + sm_off(row, kch));
            }
#pragma unroll
            for (int am = 0; am < 4; am++)
#pragma unroll
                for (int bn = 0; bn < 4; bn++)
                    mma16816(acc[am][bn], a[am], bh[bn]);
        }
        __syncthreads();
        if (c + 2 < nch) issue(c + 2, c & 1);
    }

    /* --------------------------- epilogue ---------------------------------- */
    const int g  = lane >> 2;
    const int t2 = (lane & 3) * 2;
#pragma unroll
    for (int am = 0; am < 4; am++)
#pragma unroll
        for (int bn = 0; bn < 4; bn++) {
            const int n = n0 + wn + 8*bn + t2;
#pragma unroll
            for (int half = 0; half < 2; half++) {
                const int m = m0 + wm + 16*am + g + 8*half;
                const float x0 = acc[am][bn][2*half + 0];
                const float x1 = acc[am][bn][2*half + 1];
                const size_t off = (size_t)m * ldC + n;
                if (EPI == 0) {
                    *(float2*)(C + off) = make_float2(x0, x1);
                } else if (EPI == 1) {
                    *(float2*)(C + off) = make_float2(
                        x0 / (1.f + expf(-x0)), x1 / (1.f + expf(-x1)));
                } else {
                    float2 hv = *(const float2*)(auxH + off);
                    float2 wv = *(const float2*)(auxW + n);
                    float rr = auxR[m];
                    float r0v = hv.x * rr * wv.x / (1.f + expf(-x0));
                    float r1v = hv.y * rr * wv.y / (1.f + expf(-x1));
                    *(__half2*)(Chalf + off) =
                        __halves2half2(__float2half_rn(r0v), __float2half_rn(r1v));
                }
            }
        }
}

/* ---------------------- fp32 -> fp16 plain convert -------------------------- */
__global__ void __launch_bounds__(256) conv1_kernel(
    const float4* __restrict__ src, __half2* __restrict__ hi, int n4)
{
    int i = blockIdx.x * blockDim.x + threadIdx.x;
    if (i >= n4) return;
    float4 v = src[i];
    hi[2*i]   = __halves2half2(__float2half_rn(v.x), __float2half_rn(v.y));
    hi[2*i+1] = __halves2half2(__float2half_rn(v.z), __float2half_rn(v.w));
}

/* ----------------- attention A: per-block KV outer-product sums ------------ */
__global__ void __launch_bounds__(256) attn_kvsum_kernel(
    const float* __restrict__ qkv, float* __restrict__ S)
{
    const int blk = blockIdx.x, h = blockIdx.y;
    __shared__ float Ks[64][65];
    __shared__ float Vs[64][65];
    __shared__ float tab[257];

    const int tid = threadIdx.x;
    const float slope = head_slope(h);
    for (int i = tid; i < 257; i += 256) tab[i] = expf(-slope * (float)i);

    const int tx = tid & 15, ty = tid >> 4;
    float acc[4][4];
#pragma unroll
    for (int i = 0; i < 4; i++)
#pragma unroll
        for (int j = 0; j < 4; j++) acc[i][j] = 0.f;

    for (int nc = 0; nc < 4; nc++) {
        __syncthreads();
        for (int idx = tid; idx < 1024; idx += 256) {
            int n  = idx >> 4;
            int d4 = (idx & 15) << 2;
            int ng = nc*64 + n;
            const float* base = qkv + (size_t)(blk*256 + ng) * QKVW + h*192;
            float4 k4 = *(const float4*)(base + 64 + d4);
            float  kd = tab[255 - ng];
            Ks[n][d4+0] = k4.x*kd; Ks[n][d4+1] = k4.y*kd;
            Ks[n][d4+2] = k4.z*kd; Ks[n][d4+3] = k4.w*kd;
            float4 v4 = *(const float4*)(base + 128 + d4);
            Vs[n][d4+0] = v4.x; Vs[n][d4+1] = v4.y;
            Vs[n][d4+2] = v4.z; Vs[n][d4+3] = v4.w;
        }
        __syncthreads();
#pragma unroll 8
        for (int n = 0; n < 64; n++) {
            float a[4], b[4];
#pragma unroll
            for (int i = 0; i < 4; i++) a[i] = Ks[n][ty*4 + i];
#pragma unroll
            for (int j = 0; j < 4; j++) b[j] = Vs[n][tx*4 + j];
#pragma unroll
            for (int i = 0; i < 4; i++)
#pragma unroll
                for (int j = 0; j < 4; j++) acc[i][j] += a[i]*b[j];
        }
    }
    float* sp = S + ((size_t)h*NB + blk)*4096;
#pragma unroll
    for (int i = 0; i < 4; i++)
        *(float4*)(sp + (ty*4 + i)*64 + tx*4) =
            make_float4(acc[i][0], acc[i][1], acc[i][2], acc[i][3]);
}

/* ---------------- attention B: scan of KV states across blocks ------------- */
__global__ void __launch_bounds__(256) attn_scan_kernel(
    const float* __restrict__ S, const float* __restrict__ kv0,
    float* __restrict__ KV)
{
    const int h = blockIdx.x, tid = threadIdx.x;
    const float bd = expf(-head_slope(h) * 256.f);
    float kv[16];
#pragma unroll
    for (int i = 0; i < 16; i++) kv[i] = kv0[(size_t)h*4096 + tid + i*256];
    for (int j = 0; j < NB; j++) {
        size_t base = ((size_t)h*NB + j)*4096;
#pragma unroll
        for (int i = 0; i < 16; i++) {
            KV[base + tid + i*256] = kv[i];
            kv[i] = bd*kv[i] + S[base + tid + i*256];
        }
    }
}

/* -------- attention C: per (head, block) output tile (inter + intra) ------- */
/* 512 threads: 64 row-groups of 4 rows (ty), 8 col-groups of 8 cols (tx).    */
#define ATTN_SMEM_FLOATS (288 + 2*256*65 + 3*64*65)
#define ATTN_SMEM_BYTES  (ATTN_SMEM_FLOATS * 4)

__global__ void __launch_bounds__(512) attn_out_kernel(
    const float* __restrict__ qkv, const float* __restrict__ KV,
    float* __restrict__ hid)
{
    extern __shared__ float sm[];
    float* tab = sm;
    float* Qs  = sm + 288;
    float* Ps  = Qs + 256*65;
    float* Ks  = Ps + 256*65;
    float* Vs  = Ks + 64*65;
    float* KVs = Vs + 64*65;

    const int blk = blockIdx.x, h = blockIdx.y;
    const int tid = threadIdx.x;
    const float slope = head_slope(h);
    for (int i = tid; i < 257; i += 512) tab[i] = expf(-slope * (float)i);

    for (int idx = tid; idx < 4096; idx += 512) {
        int m = idx >> 4, d4 = (idx & 15) << 2;
        float4 q4 = *(const float4*)(qkv + (size_t)(blk*256 + m)*QKVW + h*192 + d4);
        float* qp = Qs + m*65 + d4;
        qp[0] = q4.x; qp[1] = q4.y; qp[2] = q4.z; qp[3] = q4.w;
    }
    for (int idx = tid; idx < 1024; idx += 512) {
        int d = idx >> 4, e4 = (idx & 15) << 2;
        float4 v4 = *(const float4*)(KV + ((size_t)h*NB + blk)*4096 + d*64 + e4);
        float* kp = KVs + d*65 + e4;
        kp[0] = v4.x; kp[1] = v4.y; kp[2] = v4.z; kp[3] = v4.w;
    }
    __syncthreads();

    const int tx = tid & 7;
    const int ty = tid >> 3;
    const int m0 = ty * 4;
    const int wrow_hi = ((tid >> 5) << 4) + 15;

    float acc[4][8];
#pragma unroll
    for (int i = 0; i < 4; i++)
#pragma unroll
        for (int j = 0; j < 8; j++) acc[i][j] = 0.f;

#pragma unroll 4
    for (int d = 0; d < 64; d++) {
        float a[4], b[8];
#pragma unroll
        for (int i = 0; i < 4; i++) a[i] = Qs[(m0 + i)*65 + d];
#pragma unroll
        for (int j = 0; j < 8; j++) b[j] = KVs[d*65 + tx*8 + j];
#pragma unroll
        for (int i = 0; i < 4; i++)
#pragma unroll
            for (int j = 0; j < 8; j++) acc[i][j] += a[i]*b[j];
    }
#pragma unroll
    for (int i = 0; i < 4; i++) {
        float qd = tab[m0 + i + 1];
#pragma unroll
        for (int j = 0; j < 8; j++) acc[i][j] *= qd;
    }

    for (int nc = 0; nc < 4; nc++) {
        __syncthreads();
        for (int idx = tid; idx < 1024; idx += 512) {
            int n = idx >> 4, d4 = (idx & 15) << 2;
            const float* base = qkv + (size_t)(blk*256 + nc*64 + n)*QKVW + h*192;
            float4 k4 = *(const float4*)(base + 64 + d4);
            Ks[(d4+0)*65 + n] = k4.x; Ks[(d4+1)*65 + n] = k4.y;
            Ks[(d4+2)*65 + n] = k4.z; Ks[(d4+3)*65 + n] = k4.w;
            float4 v4 = *(const float4*)(base + 128 + d4);
            float* vp = Vs + n*65 + d4;
            vp[0] = v4.x; vp[1] = v4.y; vp[2] = v4.z; vp[3] = v4.w;
        }
        __syncthreads();

        if (wrow_hi >= nc*64) {              /* warp-uniform triangular skip */
            float p[4][8];
#pragma unroll
            for (int i = 0; i < 4; i++)
#pragma unroll
                for (int j = 0; j < 8; j++) p[i][j] = 0.f;
#pragma unroll 4
            for (int d = 0; d < 64; d++) {
                float a[4], b[8];
#pragma unroll
                for (int i = 0; i < 4; i++) a[i] = Qs[(m0 + i)*65 + d];
#pragma unroll
                for (int j = 0; j < 8; j++) b[j] = Ks[d*65 + tx*8 + j];
#pragma unroll
                for (int i = 0; i < 4; i++)
#pragma unroll
                    for (int j = 0; j < 8; j++) p[i][j] += a[i]*b[j];
            }
#pragma unroll
            for (int i = 0; i < 4; i++) {
                int mm = m0 + i;
#pragma unroll
                for (int j = 0; j < 8; j++) {
                    int nn = nc*64 + tx*8 + j;
                    int delta = mm - nn;
                    Ps[mm*65 + tx*8 + j] = (delta >= 0) ? p[i][j]*tab[delta] : 0.f;
                }
            }
            __syncwarp();
#pragma unroll 4
            for (int n = 0; n < 64; n++) {
                float a[4], b[8];
#pragma unroll
                for (int i = 0; i < 4; i++) a[i] = Ps[(m0 + i)*65 + n];
#pragma unroll
                for (int j = 0; j < 8; j++) b[j] = Vs[n*65 + tx*8 + j];
#pragma unroll
                for (int i = 0; i < 4; i++)
#pragma unroll
                    for (int j = 0; j < 8; j++) acc[i][j] += a[i]*b[j];
            }
        }
    }

    float* op = hid + (size_t)(blk*256) * HID + h*64;
#pragma unroll
    for (int i = 0; i < 4; i++) {
        float4* dst = (float4*)(op + (size_t)(m0 + i)*HID + tx*8);
        dst[0] = make_float4(acc[i][0], acc[i][1], acc[i][2], acc[i][3]);
        dst[1] = make_float4(acc[i][4], acc[i][5], acc[i][6], acc[i][7]);
    }
}

/* --------------------------- rmsnorm rstd vector --------------------------- */
__global__ void __launch_bounds__(256) rms_kernel(
    const float* __restrict__ hid, float* __restrict__ rstd)
{
    const int row = blockIdx.x, tid = threadIdx.x;
    const float* p = hid + (size_t)row * HID;
    float s = 0.f;
    {
        int i = tid * 8;
        float4 a = *(const float4*)(p + i);
        float4 b = *(const float4*)(p + i + 4);
        s = a.x*a.x + a.y*a.y + a.z*a.z + a.w*a.w
          + b.x*b.x + b.y*b.y + b.z*b.z + b.w*b.w;
    }
#pragma unroll
    for (int off = 16; off; off >>= 1) s += __shfl_xor_sync(~0u, s, off);
    __shared__ float red[8];
    if ((tid & 31) == 0) red[tid >> 5] = s;
    __syncthreads();
    if (tid < 8) {
        float v = red[tid];
#pragma unroll
        for (int off = 4; off; off >>= 1) v += __shfl_xor_sync(0xffu, v, off);
        if (tid == 0) rstd[row] = rsqrtf(v * (1.f / HID) + 1e-5f);
    }
}

/* --------------------------------- launch ---------------------------------- */
extern "C" void kernel_launch(void* const* d_in, const int* in_sizes, int n_in,
                              void* d_out, int out_size)
{
    (void)in_sizes; (void)n_in; (void)out_size;
    const float* hs   = (const float*)d_in[0];
    const float* kv0  = (const float*)d_in[1];
    const float* Wqkv = (const float*)d_in[2];
    const float* Wg   = (const float*)d_in[3];
    const float* Wo   = (const float*)d_in[4];
    const float* nw   = (const float*)d_in[5];
    float* out = (float*)d_out;

    float *qkv, *S, *KV, *hid, *rstd;
    __half *hs_h, *wq_h, *wg_h, *wo_h, *tmp_h;
    cudaGetSymbolAddress((void**)&qkv,  g_qkv);
    cudaGetSymbolAddress((void**)&S,    g_S);
    cudaGetSymbolAddress((void**)&KV,   g_KV);
    cudaGetSymbolAddress((void**)&hid,  g_hid);
    cudaGetSymbolAddress((void**)&rstd, g_rstd);
    cudaGetSymbolAddress((void**)&hs_h, g_hs_h);
    cudaGetSymbolAddress((void**)&wq_h, g_wqkv_h);
    cudaGetSymbolAddress((void**)&wg_h, g_wg_h);
    cudaGetSymbolAddress((void**)&wo_h, g_wo_h);
    cudaGetSymbolAddress((void**)&tmp_h, g_tmp_h);

    cudaFuncSetAttribute(attn_out_kernel,
                         cudaFuncAttributeMaxDynamicSharedMemorySize, ATTN_SMEM_BYTES);
    cudaFuncSetAttribute(mma_gemm_kernel<0>,
                         cudaFuncAttributeMaxDynamicSharedMemorySize, GEMM_SMEM);
    cudaFuncSetAttribute(mma_gemm_kernel<1>,
                         cudaFuncAttributeMaxDynamicSharedMemorySize, GEMM_SMEM);
    cudaFuncSetAttribute(mma_gemm_kernel<2>,
                         cudaFuncAttributeMaxDynamicSharedMemorySize, GEMM_SMEM);

    /* 0. fp16 conversions */
    conv1_kernel<<<(NTOK*HID/4 + 255)/256, 256>>>(
        (const float4*)hs, (__half2*)hs_h, NTOK*HID/4);
    conv1_kernel<<<(QKVW*HID/4 + 255)/256, 256>>>(
        (const float4*)Wqkv, (__half2*)wq_h, QKVW*HID/4);
    conv1_kernel<<<(HID*HID/4 + 255)/256, 256>>>(
        (const float4*)Wg, (__half2*)wg_h, HID*HID/4);
    conv1_kernel<<<(HID*HID/4 + 255)/256, 256>>>(
        (const float4*)Wo, (__half2*)wo_h, HID*HID/4);

    /* 1. qkv = silu(hs @ Wqkv^T) */
    mma_gemm_kernel<1><<<dim3(QKVW/BN, NTOK/BM), 256, GEMM_SMEM>>>(
        hs_h, wq_h, HID, QKVW, qkv, nullptr, nullptr, nullptr, nullptr);

    /* 2-4. lightning attention */
    attn_kvsum_kernel<<<dim3(NB, NH), 256>>>(qkv, S);
    attn_scan_kernel<<<NH, 256>>>(S, kv0, KV);
    attn_out_kernel<<<dim3(NB, NH), 512, ATTN_SMEM_BYTES>>>(qkv, KV, hid);

    /* 5. rmsnorm scale vector */
    rms_kernel<<<NTOK, 256>>>(hid, rstd);

    /* 6. tmp = sigmoid(hs @ Wg^T) * hid * rstd * nw -> fp16 */
    mma_gemm_kernel<2><<<dim3(HID/BN, NTOK/BM), 256, GEMM_SMEM>>>(
        hs_h, wg_h, HID, HID, nullptr, tmp_h, hid, rstd, nw);

    /* 7. out = tmp @ Wo^T */
    mma_gemm_kernel<0><<<dim3(HID/BN, NTOK/BM), 256, GEMM_SMEM>>>(
        tmp_h, wo_h, HID, HID, out, nullptr, nullptr, nullptr, nullptr);
}

// round 9
// speedup vs baseline: 2.4351x; 1.2359x over previous
#include <cuda_runtime.h>
#include <cuda_fp16.h>
#include <math.h>
#include <stdint.h>

#define HID   2048
#define NTOK  8192
#define NH    32
#define HD    64
#define NB    32            /* 8192 / 256 */
#define QKVW  (3*HID)       /* 6144 */

/* ---------------- GEMM tiling (mma.sync fp16, single pass) ----------------- */
#define BM 128
#define BN 128
#define BK 32
#define ST_A 0
#define ST_B 8192
#define STAGE_BYTES 16384           /* 8+8 KB */
#define GEMM_SMEM (2*STAGE_BYTES)   /* 32 KB */

/* ------------------------- scratch (device globals) ------------------------ */
__device__ float g_S  [(size_t)NH * NB * HD * HD];
__device__ float g_KV [(size_t)NH * NB * HD * HD];
__device__ float g_hid[(size_t)NTOK * HID];
__device__ float g_rstd[NTOK];
__device__ __half g_qkv_h [(size_t)NTOK * QKVW];
__device__ __half g_hs_h  [(size_t)NTOK * HID];
__device__ __half g_wqkv_h[(size_t)QKVW * HID];
__device__ __half g_wg_h  [(size_t)HID * HID];
__device__ __half g_wo_h  [(size_t)HID * HID];
__device__ __half g_tmp_h [(size_t)NTOK * HID];

/* ------------------------------ PTX helpers -------------------------------- */
__device__ __forceinline__ uint32_t smem_u32(const void* p) {
    uint32_t a;
    asm("{ .reg .u64 t; cvta.to.shared.u64 t, %1; cvt.u32.u64 %0, t; }"
        : "=r"(a) : "l"(p));
    return a;
}
__device__ __forceinline__ void cp16(uint32_t dst, const void* src) {
    asm volatile("cp.async.cg.shared.global [%0], [%1], 16;"
                 :: "r"(dst), "l"(src));
}
#define CP_COMMIT()  asm volatile("cp.async.commit_group;" ::: "memory")
#define CP_WAIT(n)   asm volatile("cp.async.wait_group %0;" :: "n"(n) : "memory")

__device__ __forceinline__ void ldsm4(uint32_t* r, uint32_t addr) {
    asm volatile("ldmatrix.sync.aligned.m8n8.x4.shared.b16 {%0,%1,%2,%3}, [%4];"
                 : "=r"(r[0]), "=r"(r[1]), "=r"(r[2]), "=r"(r[3]) : "r"(addr));
}
__device__ __forceinline__ void mma16816(float* d, const uint32_t* a,
                                         const uint32_t* b) {
    asm volatile(
        "mma.sync.aligned.m16n8k16.row.col.f32.f16.f16.f32 "
        "{%0,%1,%2,%3}, {%4,%5,%6,%7}, {%8,%9}, {%0,%1,%2,%3};"
        : "+f"(d[0]), "+f"(d[1]), "+f"(d[2]), "+f"(d[3])
        : "r"(a[0]), "r"(a[1]), "r"(a[2]), "r"(a[3]), "r"(b[0]), "r"(b[1]));
}

__device__ __forceinline__ float head_slope(int h) {
    return exp2f(-0.25f * (float)(h + 1)) * 1.00001f;
}

/* swizzled smem layout: (row, kch) -> 16B slot; rt = number of 8-row tiles */
__device__ __forceinline__ uint32_t smoff(int row, int kch, int rt) {
    return (uint32_t)((kch*rt + (row >> 3))*128 + (((row & 7) ^ (kch & 7)) << 4));
}

/* ---------------------- mma.sync fp16 single-pass GEMM --------------------- */
/* C[m,n] = epi( sum_k A[m,k]*B[n,k] ), A=[M,K] fp16, B=[N,K] fp16.
   EPI 0: C fp32.  EPI 1: silu -> Chalf fp16.
   EPI 2: sigmoid(x)*auxH[m,n]*auxR[m]*auxW[n] -> Chalf fp16.                */
template<int EPI>
__global__ void __launch_bounds__(256, 2) mma_gemm_kernel(
    const __half* __restrict__ Ah, const __half* __restrict__ Bh,
    int K, int ldC,
    float* __restrict__ C, __half* __restrict__ Chalf,
    const float* __restrict__ auxH, const float* __restrict__ auxR,
    const float* __restrict__ auxW)
{
    extern __shared__ char smraw[];
    const uint32_t smu = smem_u32(smraw);
    const int tid  = threadIdx.x;
    const int lane = tid & 31;
    const int wid  = tid >> 5;
    const int m0   = blockIdx.y * BM;
    const int n0   = blockIdx.x * BN;
    const int wm   = (wid >> 2) * 64;
    const int wn   = (wid & 3)  * 32;

    const int r0 = tid >> 2;
    const int kq = tid & 3;

    float acc[4][4][4];
#pragma unroll
    for (int i = 0; i < 4; i++)
#pragma unroll
        for (int j = 0; j < 4; j++)
#pragma unroll
            for (int v = 0; v < 4; v++) acc[i][j][v] = 0.f;

    const int nch = K / BK;

    auto issue = [&](int c, int s) {
        const int kc = c * BK;
        const uint32_t sb = smu + (uint32_t)s * STAGE_BYTES;
#pragma unroll
        for (int i = 0; i < 2; i++) {
            const int r = r0 + 64 * i;
            const uint32_t wo = smoff(r, kq, 16);
            const size_t ga = (size_t)(m0 + r) * K + kc + kq * 8;
            const size_t gb = (size_t)(n0 + r) * K + kc + kq * 8;
            cp16(sb + ST_A + wo, Ah + ga);
            cp16(sb + ST_B + wo, Bh + gb);
        }
        CP_COMMIT();
    };

    issue(0, 0);
    if (nch > 1) issue(1, 1);

    for (int c = 0; c < nch; c++) {
        if (c + 1 < nch) { CP_WAIT(1); } else { CP_WAIT(0); }
        __syncthreads();

        const uint32_t sb = smu + (uint32_t)(c & 1) * STAGE_BYTES;
#pragma unroll
        for (int ks = 0; ks < 2; ks++) {
            uint32_t a[4][4], bh[4][2];
#pragma unroll
            for (int half = 0; half < 2; half++) {
                const int n   = wn + 16*half + ((lane >> 4) << 3) + (lane & 7);
                const int kch = 2*ks + ((lane >> 3) & 1);
                uint32_t t4[4];
                ldsm4(t4, sb + ST_B + smoff(n, kch, 16));
                bh[2*half][0] = t4[0]; bh[2*half][1] = t4[1];
                bh[2*half+1][0] = t4[2]; bh[2*half+1][1] = t4[3];
            }
#pragma unroll
            for (int am = 0; am < 4; am++) {
                const int row = wm + 16*am + (lane & 15);
                const int kch = 2*ks + (lane >> 4);
                ldsm4(a[am], sb + ST_A + smoff(row, kch, 16));
            }
#pragma unroll
            for (int am = 0; am < 4; am++)
#pragma unroll
                for (int bn = 0; bn < 4; bn++)
                    mma16816(acc[am][bn], a[am], bh[bn]);
        }
        __syncthreads();
        if (c + 2 < nch) issue(c + 2, c & 1);
    }

    const int g  = lane >> 2;
    const int t2 = (lane & 3) * 2;
#pragma unroll
    for (int am = 0; am < 4; am++)
#pragma unroll
        for (int bn = 0; bn < 4; bn++) {
            const int n = n0 + wn + 8*bn + t2;
#pragma unroll
            for (int half = 0; half < 2; half++) {
                const int m = m0 + wm + 16*am + g + 8*half;
                const float x0 = acc[am][bn][2*half + 0];
                const float x1 = acc[am][bn][2*half + 1];
                const size_t off = (size_t)m * ldC + n;
                if (EPI == 0) {
                    *(float2*)(C + off) = make_float2(x0, x1);
                } else if (EPI == 1) {
                    float s0 = x0 / (1.f + expf(-x0));
                    float s1 = x1 / (1.f + expf(-x1));
                    *(__half2*)(Chalf + off) =
                        __halves2half2(__float2half_rn(s0), __float2half_rn(s1));
                } else {
                    float2 hv = *(const float2*)(auxH + off);
                    float2 wv = *(const float2*)(auxW + n);
                    float rr = auxR[m];
                    float r0v = hv.x * rr * wv.x / (1.f + expf(-x0));
                    float r1v = hv.y * rr * wv.y / (1.f + expf(-x1));
                    *(__half2*)(Chalf + off) =
                        __halves2half2(__float2half_rn(r0v), __float2half_rn(r1v));
                }
            }
        }
}

/* ---------------------- fp32 -> fp16 plain convert -------------------------- */
__global__ void __launch_bounds__(256) conv1_kernel(
    const float4* __restrict__ src, __half2* __restrict__ hi, int n4)
{
    int i = blockIdx.x * blockDim.x + threadIdx.x;
    if (i >= n4) return;
    float4 v = src[i];
    hi[2*i]   = __halves2half2(__float2half_rn(v.x), __float2half_rn(v.y));
    hi[2*i+1] = __halves2half2(__float2half_rn(v.z), __float2half_rn(v.w));
}

/* ----------------- attention A: per-block KV outer-product sums ------------ */
__global__ void __launch_bounds__(256) attn_kvsum_kernel(
    const __half* __restrict__ qkvh, float* __restrict__ S)
{
    const int blk = blockIdx.x, h = blockIdx.y;
    __shared__ float Ks[64][65];
    __shared__ float Vs[64][65];
    __shared__ float tab[257];

    const int tid = threadIdx.x;
    const float slope = head_slope(h);
    for (int i = tid; i < 257; i += 256) tab[i] = expf(-slope * (float)i);

    const int tx = tid & 15, ty = tid >> 4;
    float acc[4][4];
#pragma unroll
    for (int i = 0; i < 4; i++)
#pragma unroll
        for (int j = 0; j < 4; j++) acc[i][j] = 0.f;

    for (int nc = 0; nc < 4; nc++) {
        __syncthreads();
        for (int idx = tid; idx < 1024; idx += 256) {
            int n  = idx >> 4;
            int d4 = (idx & 15) << 2;
            int ng = nc*64 + n;
            const __half* base = qkvh + (size_t)(blk*256 + ng) * QKVW + h*192;
            uint2 kr = *(const uint2*)(base + 64 + d4);
            __half2 k01 = *(__half2*)&kr.x, k23 = *(__half2*)&kr.y;
            float2 f01 = __half22float2(k01), f23 = __half22float2(k23);
            float kd = tab[255 - ng];
            Ks[n][d4+0] = f01.x*kd; Ks[n][d4+1] = f01.y*kd;
            Ks[n][d4+2] = f23.x*kd; Ks[n][d4+3] = f23.y*kd;
            uint2 vr = *(const uint2*)(base + 128 + d4);
            __half2 v01 = *(__half2*)&vr.x, v23 = *(__half2*)&vr.y;
            float2 g01 = __half22float2(v01), g23 = __half22float2(v23);
            Vs[n][d4+0] = g01.x; Vs[n][d4+1] = g01.y;
            Vs[n][d4+2] = g23.x; Vs[n][d4+3] = g23.y;
        }
        __syncthreads();
#pragma unroll 8
        for (int n = 0; n < 64; n++) {
            float a[4], b[4];
#pragma unroll
            for (int i = 0; i < 4; i++) a[i] = Ks[n][ty*4 + i];
#pragma unroll
            for (int j = 0; j < 4; j++) b[j] = Vs[n][tx*4 + j];
#pragma unroll
            for (int i = 0; i < 4; i++)
#pragma unroll
                for (int j = 0; j < 4; j++) acc[i][j] += a[i]*b[j];
        }
    }
    float* sp = S + ((size_t)h*NB + blk)*4096;
#pragma unroll
    for (int i = 0; i < 4; i++)
        *(float4*)(sp + (ty*4 + i)*64 + tx*4) =
            make_float4(acc[i][0], acc[i][1], acc[i][2], acc[i][3]);
}

/* ---------------- attention B: scan of KV states across blocks ------------- */
__global__ void __launch_bounds__(256) attn_scan_kernel(
    const float* __restrict__ S, const float* __restrict__ kv0,
    float* __restrict__ KV)
{
    const int h = blockIdx.x, tid = threadIdx.x;
    const float bd = expf(-head_slope(h) * 256.f);
    float kv[16];
#pragma unroll
    for (int i = 0; i < 16; i++) kv[i] = kv0[(size_t)h*4096 + tid + i*256];
    for (int j = 0; j < NB; j++) {
        size_t base = ((size_t)h*NB + j)*4096;
#pragma unroll
        for (int i = 0; i < 16; i++) {
            KV[base + tid + i*256] = kv[i];
            kv[i] = bd*kv[i] + S[base + tid + i*256];
        }
    }
}

/* --------- attention C: tensor-core tile (inter + masked intra) ------------ */
/* smem layout (bytes) */
#define ATN_TAB  0
#define ATN_QS   1280
#define ATN_PS   (ATN_QS + 32768)
#define ATN_KS   (ATN_PS + 32768)
#define ATN_VT   (ATN_KS + 8192)
#define ATN_KVT  (ATN_VT + 8192)
#define ATN_SMEM (ATN_KVT + 8192)     /* 91392 */

__global__ void __launch_bounds__(256) attn_out_kernel(
    const __half* __restrict__ qkvh, const float* __restrict__ KV,
    float* __restrict__ hid)
{
    extern __shared__ char smraw[];
    const uint32_t smu = smem_u32(smraw);
    float* tab = (float*)smraw;

    const int blk = blockIdx.x, h = blockIdx.y;
    const int tid = threadIdx.x;
    const int lane = tid & 31, w = tid >> 5;
    const float slope = head_slope(h);
    for (int i = tid; i < 257; i += 256) tab[i] = expf(-slope * (float)i);

    /* Q tile 256x64 fp16 -> swizzled Qs (cp.async) */
    {
        const int row = tid >> 3, kch = tid & 7;
        const __half* src = qkvh + (size_t)(blk*256)*QKVW + h*192 + kch*8;
#pragma unroll
        for (int i = 0; i < 8; i++) {
            const int r = row + 32*i;
            cp16(smu + ATN_QS + smoff(r, kch, 32), src + (size_t)r*QKVW);
        }
        CP_COMMIT();
    }
    /* KVt[e][d] fp16 from fp32 KV[d][e] */
    {
        const float* kvp = KV + ((size_t)h*NB + blk)*4096;
#pragma unroll
        for (int i = 0; i < 16; i++) {
            const int idx = tid + 256*i;
            const int e = idx & 63, d = idx >> 6;
            *(__half*)(smraw + ATN_KVT + smoff(e, d >> 3, 8) + (d & 7)*2) =
                __float2half_rn(kvp[d*64 + e]);
        }
    }
    CP_WAIT(0);
    __syncthreads();

    const int m0 = w * 32;
    const int g = lane >> 2, t2 = (lane & 3) * 2;

    float acc[2][8][4];
#pragma unroll
    for (int i = 0; i < 2; i++)
#pragma unroll
        for (int j = 0; j < 8; j++)
#pragma unroll
            for (int v = 0; v < 4; v++) acc[i][j][v] = 0.f;

    /* inter: Q @ KVt */
#pragma unroll
    for (int ks = 0; ks < 4; ks++) {
        uint32_t a[2][4], b[8][2];
#pragma unroll
        for (int half = 0; half < 4; half++) {
            const int e   = 16*half + ((lane >> 4) << 3) + (lane & 7);
            const int kch = 2*ks + ((lane >> 3) & 1);
            uint32_t t4[4];
            ldsm4(t4, smu + ATN_KVT + smoff(e, kch, 8));
            b[2*half][0] = t4[0]; b[2*half][1] = t4[1];
            b[2*half+1][0] = t4[2]; b[2*half+1][1] = t4[3];
        }
#pragma unroll
        for (int am = 0; am < 2; am++) {
            const int row = m0 + 16*am + (lane & 15);
            const int kch = 2*ks + (lane >> 4);
            ldsm4(a[am], smu + ATN_QS + smoff(row, kch, 32));
        }
#pragma unroll
        for (int am = 0; am < 2; am++)
#pragma unroll
            for (int bn = 0; bn < 8; bn++)
                mma16816(acc[am][bn], a[am], b[bn]);
    }
    /* scale inter by q_decay = tab[m_local + 1] */
#pragma unroll
    for (int am = 0; am < 2; am++)
#pragma unroll
        for (int half = 0; half < 2; half++) {
            const float qd = tab[m0 + 16*am + g + 8*half + 1];
#pragma unroll
            for (int bn = 0; bn < 8; bn++) {
                acc[am][bn][2*half+0] *= qd;
                acc[am][bn][2*half+1] *= qd;
            }
        }

    for (int nc = 0; nc < 4; nc++) {
        __syncthreads();
        /* K chunk (cp.async) */
#pragma unroll
        for (int i = 0; i < 2; i++) {
            const int idx = tid + 256*i;
            const int n = idx >> 3, kch = idx & 7;
            cp16(smu + ATN_KS + smoff(n, kch, 8),
                 qkvh + (size_t)(blk*256 + nc*64 + n)*QKVW + h*192 + 64 + kch*8);
        }
        CP_COMMIT();
        /* V chunk transposed: Vt[e][n] */
#pragma unroll
        for (int i = 0; i < 16; i++) {
            const int idx = tid + 256*i;
            const int e = idx & 63, n = idx >> 6;
            *(__half*)(smraw + ATN_VT + smoff(e, n >> 3, 8) + (n & 7)*2) =
                qkvh[(size_t)(blk*256 + nc*64 + n)*QKVW + h*192 + 128 + e];
        }
        CP_WAIT(0);
        __syncthreads();

        if (m0 + 31 >= nc*64) {          /* warp-uniform triangular skip */
            float p[2][8][4];
#pragma unroll
            for (int i = 0; i < 2; i++)
#pragma unroll
                for (int j = 0; j < 8; j++)
#pragma unroll
                    for (int v = 0; v < 4; v++) p[i][j][v] = 0.f;
            /* P = Q @ K^T */
#pragma unroll
            for (int ks = 0; ks < 4; ks++) {
                uint32_t a[2][4], b[8][2];
#pragma unroll
                for (int half = 0; half < 4; half++) {
                    const int n   = 16*half + ((lane >> 4) << 3) + (lane & 7);
                    const int kch = 2*ks + ((lane >> 3) & 1);
                    uint32_t t4[4];
                    ldsm4(t4, smu + ATN_KS + smoff(n, kch, 8));
                    b[2*half][0] = t4[0]; b[2*half][1] = t4[1];
                    b[2*half+1][0] = t4[2]; b[2*half+1][1] = t4[3];
                }
#pragma unroll
                for (int am = 0; am < 2; am++) {
                    const int row = m0 + 16*am + (lane & 15);
                    const int kch = 2*ks + (lane >> 4);
                    ldsm4(a[am], smu + ATN_QS + smoff(row, kch, 32));
                }
#pragma unroll
                for (int am = 0; am < 2; am++)
#pragma unroll
                    for (int bn = 0; bn < 8; bn++)
                        mma16816(p[am][bn], a[am], b[bn]);
            }
            /* decayed causal mask -> fp16 Ps (warp-private rows) */
#pragma unroll
            for (int am = 0; am < 2; am++)
#pragma unroll
                for (int half = 0; half < 2; half++) {
                    const int mm = m0 + 16*am + g + 8*half;
#pragma unroll
                    for (int bn = 0; bn < 8; bn++) {
                        const int nnc = 8*bn + t2;
                        const int d0 = mm - (nc*64 + nnc);
                        const int d1 = d0 - 1;
                        const float v0 = (d0 >= 0) ? p[am][bn][2*half+0]*tab[d0] : 0.f;
                        const float v1 = (d1 >= 0) ? p[am][bn][2*half+1]*tab[d1] : 0.f;
                        *(__half2*)(smraw + ATN_PS + smoff(mm, nnc >> 3, 32)
                                    + (nnc & 7)*2) =
                            __halves2half2(__float2half_rn(v0), __float2half_rn(v1));
                    }
                }
            __syncwarp();
            /* out += P @ V  (A = Ps rows of this warp, B = Vt) */
#pragma unroll
            for (int ks = 0; ks < 4; ks++) {
                uint32_t a[2][4], b[8][2];
#pragma unroll
                for (int half = 0; half < 4; half++) {
                    const int e   = 16*half + ((lane >> 4) << 3) + (lane & 7);
                    const int kch = 2*ks + ((lane >> 3) & 1);
                    uint32_t t4[4];
                    ldsm4(t4, smu + ATN_VT + smoff(e, kch, 8));
                    b[2*half][0] = t4[0]; b[2*half][1] = t4[1];
                    b[2*half+1][0] = t4[2]; b[2*half+1][1] = t4[3];
                }
#pragma unroll
                for (int am = 0; am < 2; am++) {
                    const int row = m0 + 16*am + (lane & 15);
                    const int kch = 2*ks + (lane >> 4);
                    ldsm4(a[am], smu + ATN_PS + smoff(row, kch, 32));
                }
#pragma unroll
                for (int am = 0; am < 2; am++)
#pragma unroll
                    for (int bn = 0; bn < 8; bn++)
                        mma16816(acc[am][bn], a[am], b[bn]);
            }
        }
    }

    /* store out tile (fp32 hid) */
#pragma unroll
    for (int am = 0; am < 2; am++)
#pragma unroll
        for (int bn = 0; bn < 8; bn++)
#pragma unroll
            for (int half = 0; half < 2; half++) {
                const int mm = m0 + 16*am + g + 8*half;
                const int col = h*64 + 8*bn + t2;
                *(float2*)(hid + (size_t)(blk*256 + mm)*HID + col) =
                    make_float2(acc[am][bn][2*half+0], acc[am][bn][2*half+1]);
            }
}

/* --------------------------- rmsnorm rstd vector --------------------------- */
__global__ void __launch_bounds__(256) rms_kernel(
    const float* __restrict__ hid, float* __restrict__ rstd)
{
    const int row = blockIdx.x, tid = threadIdx.x;
    const float* p = hid + (size_t)row * HID;
    float s = 0.f;
    {
        int i = tid * 8;
        float4 a = *(const float4*)(p + i);
        float4 b = *(const float4*)(p + i + 4);
        s = a.x*a.x + a.y*a.y + a.z*a.z + a.w*a.w
          + b.x*b.x + b.y*b.y + b.z*b.z + b.w*b.w;
    }
#pragma unroll
    for (int off = 16; off; off >>= 1) s += __shfl_xor_sync(~0u, s, off);
    __shared__ float red[8];
    if ((tid & 31) == 0) red[tid >> 5] = s;
    __syncthreads();
    if (tid < 8) {
        float v = red[tid];
#pragma unroll
        for (int off = 4; off; off >>= 1) v += __shfl_xor_sync(0xffu, v, off);
        if (tid == 0) rstd[row] = rsqrtf(v * (1.f / HID) + 1e-5f);
    }
}

/* --------------------------------- launch ---------------------------------- */
extern "C" void kernel_launch(void* const* d_in, const int* in_sizes, int n_in,
                              void* d_out, int out_size)
{
    (void)in_sizes; (void)n_in; (void)out_size;
    const float* hs   = (const float*)d_in[0];
    const float* kv0  = (const float*)d_in[1];
    const float* Wqkv = (const float*)d_in[2];
    const float* Wg   = (const float*)d_in[3];
    const float* Wo   = (const float*)d_in[4];
    const float* nw   = (const float*)d_in[5];
    float* out = (float*)d_out;

    float *S, *KV, *hid, *rstd;
    __half *qkv_h, *hs_h, *wq_h, *wg_h, *wo_h, *tmp_h;
    cudaGetSymbolAddress((void**)&S,    g_S);
    cudaGetSymbolAddress((void**)&KV,   g_KV);
    cudaGetSymbolAddress((void**)&hid,  g_hid);
    cudaGetSymbolAddress((void**)&rstd, g_rstd);
    cudaGetSymbolAddress((void**)&qkv_h, g_qkv_h);
    cudaGetSymbolAddress((void**)&hs_h, g_hs_h);
    cudaGetSymbolAddress((void**)&wq_h, g_wqkv_h);
    cudaGetSymbolAddress((void**)&wg_h, g_wg_h);
    cudaGetSymbolAddress((void**)&wo_h, g_wo_h);
    cudaGetSymbolAddress((void**)&tmp_h, g_tmp_h);

    cudaFuncSetAttribute(attn_out_kernel,
                         cudaFuncAttributeMaxDynamicSharedMemorySize, ATN_SMEM);
    cudaFuncSetAttribute(mma_gemm_kernel<0>,
                         cudaFuncAttributeMaxDynamicSharedMemorySize, GEMM_SMEM);
    cudaFuncSetAttribute(mma_gemm_kernel<1>,
                         cudaFuncAttributeMaxDynamicSharedMemorySize, GEMM_SMEM);
    cudaFuncSetAttribute(mma_gemm_kernel<2>,
                         cudaFuncAttributeMaxDynamicSharedMemorySize, GEMM_SMEM);

    /* 0. fp16 conversions */
    conv1_kernel<<<(NTOK*HID/4 + 255)/256, 256>>>(
        (const float4*)hs, (__half2*)hs_h, NTOK*HID/4);
    conv1_kernel<<<(QKVW*HID/4 + 255)/256, 256>>>(
        (const float4*)Wqkv, (__half2*)wq_h, QKVW*HID/4);
    conv1_kernel<<<(HID*HID/4 + 255)/256, 256>>>(
        (const float4*)Wg, (__half2*)wg_h, HID*HID/4);
    conv1_kernel<<<(HID*HID/4 + 255)/256, 256>>>(
        (const float4*)Wo, (__half2*)wo_h, HID*HID/4);

    /* 1. qkv = silu(hs @ Wqkv^T) -> fp16 */
    mma_gemm_kernel<1><<<dim3(QKVW/BN, NTOK/BM), 256, GEMM_SMEM>>>(
        hs_h, wq_h, HID, QKVW, nullptr, qkv_h, nullptr, nullptr, nullptr);

    /* 2-4. lightning attention */
    attn_kvsum_kernel<<<dim3(NB, NH), 256>>>(qkv_h, S);
    attn_scan_kernel<<<NH, 256>>>(S, kv0, KV);
    attn_out_kernel<<<dim3(NB, NH), 256, ATN_SMEM>>>(qkv_h, KV, hid);

    /* 5. rmsnorm scale vector */
    rms_kernel<<<NTOK, 256>>>(hid, rstd);

    /* 6. tmp = sigmoid(hs @ Wg^T) * hid * rstd * nw -> fp16 */
    mma_gemm_kernel<2><<<dim3(HID/BN, NTOK/BM), 256, GEMM_SMEM>>>(
        hs_h, wg_h, HID, HID, nullptr, tmp_h, hid, rstd, nw);

    /* 7. out = tmp @ Wo^T */
    mma_gemm_kernel<0><<<dim3(HID/BN, NTOK/BM), 256, GEMM_SMEM>>>(
        tmp_h, wo_h, HID, HID, out, nullptr, nullptr, nullptr, nullptr);
}